// round 4
// baseline (speedup 1.0000x reference)
#include <cuda_runtime.h>
#include <cuda_bf16.h>
#include <math.h>
#include <stdint.h>

// Problem constants
#define SEQ   4096
#define DM    1024
#define NH    16
#define DH    64

// ---------------- scratch (no allocations allowed) ----------------
__device__ float g_Q[SEQ * DM];
__device__ float g_K[SEQ * DM];
__device__ float g_V[SEQ * DM];

__device__ __nv_bfloat16 g_xh[SEQ * DM],  g_xl[SEQ * DM];
__device__ __nv_bfloat16 g_wh[3 * DM * DM], g_wl[3 * DM * DM];   // Wq,Wk,Wv stacked rows
__device__ __nv_bfloat16 g_woh[DM * DM],  g_wol[DM * DM];
__device__ __nv_bfloat16 g_qh[SEQ * DM],  g_ql[SEQ * DM];        // roped, pre-scaled 1/8
__device__ __nv_bfloat16 g_kh[SEQ * DM],  g_kl[SEQ * DM];
__device__ __nv_bfloat16 g_vh[SEQ * DM],  g_vl[SEQ * DM];
__device__ __nv_bfloat16 g_ah[SEQ * DM],  g_al[SEQ * DM];        // attention out split

// ---------------- low-level helpers ----------------
__device__ __forceinline__ uint32_t smem_u32(const void* p) {
    uint32_t a;
    asm("{ .reg .u64 t; cvta.to.shared.u64 t, %1; cvt.u32.u64 %0, t; }" : "=r"(a) : "l"(p));
    return a;
}
__device__ __forceinline__ void cp_async16(uint32_t sa, const void* ga) {
    asm volatile("cp.async.cg.shared.global [%0], [%1], 16;" :: "r"(sa), "l"(ga));
}
#define CP_COMMIT() asm volatile("cp.async.commit_group;" ::: "memory")
#define CP_WAIT1()  asm volatile("cp.async.wait_group 1;" ::: "memory")
#define CP_WAIT0()  asm volatile("cp.async.wait_group 0;" ::: "memory")

__device__ __forceinline__ void ldsm_x4(uint32_t* r, uint32_t addr) {
    asm volatile("ldmatrix.sync.aligned.m8n8.x4.shared.b16 {%0,%1,%2,%3}, [%4];"
        : "=r"(r[0]), "=r"(r[1]), "=r"(r[2]), "=r"(r[3]) : "r"(addr));
}
__device__ __forceinline__ void ldsm_x4t(uint32_t* r, uint32_t addr) {
    asm volatile("ldmatrix.sync.aligned.m8n8.x4.trans.shared.b16 {%0,%1,%2,%3}, [%4];"
        : "=r"(r[0]), "=r"(r[1]), "=r"(r[2]), "=r"(r[3]) : "r"(addr));
}
__device__ __forceinline__ void mma16816(float* d, const uint32_t* a, const uint32_t* b) {
    asm volatile("mma.sync.aligned.m16n8k16.row.col.f32.bf16.bf16.f32 "
        "{%0,%1,%2,%3}, {%4,%5,%6,%7}, {%8,%9}, {%0,%1,%2,%3};"
        : "+f"(d[0]), "+f"(d[1]), "+f"(d[2]), "+f"(d[3])
        : "r"(a[0]), "r"(a[1]), "r"(a[2]), "r"(a[3]), "r"(b[0]), "r"(b[1]));
}
__device__ __forceinline__ uint32_t pack2(__nv_bfloat16 a, __nv_bfloat16 b) {
    __nv_bfloat162 t; t.x = a; t.y = b;
    uint32_t u; memcpy(&u, &t, 4); return u;
}
__device__ __forceinline__ void split1(float v, __nv_bfloat16& h, __nv_bfloat16& l) {
    h = __float2bfloat16(v);
    l = __float2bfloat16(v - __bfloat162float(h));
}

// ---------------- hi/lo convert kernel (inputs) ----------------
__global__ void cvt_kernel(const float* __restrict__ src, int sel) {
    __nv_bfloat16 *hi, *lo;
    switch (sel) {
        case 0: hi = g_xh;               lo = g_xl;               break;
        case 1: hi = g_wh;               lo = g_wl;               break;
        case 2: hi = g_wh + DM * DM;     lo = g_wl + DM * DM;     break;
        case 3: hi = g_wh + 2 * DM * DM; lo = g_wl + 2 * DM * DM; break;
        default: hi = g_woh;             lo = g_wol;              break;
    }
    int i = (blockIdx.x * 256 + threadIdx.x) * 4;
    float4 v = *(const float4*)&src[i];
    __nv_bfloat16 h0, l0, h1, l1, h2, l2, h3, l3;
    split1(v.x, h0, l0); split1(v.y, h1, l1);
    split1(v.z, h2, l2); split1(v.w, h3, l3);
    *(uint32_t*)&hi[i]     = pack2(h0, h1);
    *(uint32_t*)&hi[i + 2] = pack2(h2, h3);
    *(uint32_t*)&lo[i]     = pack2(l0, l1);
    *(uint32_t*)&lo[i + 2] = pack2(l2, l3);
}

// ---------------- HMMA split-bf16 NT GEMM ----------------
// C[m,n] = sum_k A[m,k]*B[n,k]; BM=BN=128, BK=64, 128 threads, 4 warps of 64x64.
#define SKB 144                    // smem row stride bytes (72 bf16, conflict-free ldsm)
#define GTILE (128 * SKB)          // 18432 B per matrix tile
#define GSTAGE (2 * GTILE)         // A+B
#define GEMM_SMEM (2 * GSTAGE)     // double buffer: 73728

__device__ __forceinline__ void gemm_issue(int t, uint32_t st,
                                           const __nv_bfloat16* A, const __nv_bfloat16* B) {
#pragma unroll
    for (int i = 0; i < 8; i++) {
        int idx = t + i * 128;
        int row = idx >> 3, ch = idx & 7;
        cp_async16(st + row * SKB + ch * 16,
                   (const char*)A + (size_t)row * (DM * 2) + ch * 16);
        cp_async16(st + GTILE + row * SKB + ch * 16,
                   (const char*)B + (size_t)row * (DM * 2) + ch * 16);
    }
    CP_COMMIT();
}

__global__ __launch_bounds__(128)
void mma_gemm_kernel(int which, float* __restrict__ outp) {
    extern __shared__ char dsm[];
    const uint32_t sbase = smem_u32(dsm);
    const int t = threadIdx.x, lane = t & 31, wid = t >> 5;
    const int nt = blockIdx.x, mt = blockIdx.y;
    const int m0 = mt * 128, n0 = nt * 128;

    const __nv_bfloat16 *pA[3], *pB[3];
    float* C; int ccol;
    if (which == 0) {
        pA[0] = g_xh; pA[1] = g_xh; pA[2] = g_xl;
        const __nv_bfloat16* bh = g_wh + (size_t)n0 * DM;
        const __nv_bfloat16* bl = g_wl + (size_t)n0 * DM;
        pB[0] = bh; pB[1] = bl; pB[2] = bh;
        int mat = nt >> 3;
        C = (mat == 0) ? g_Q : (mat == 1 ? g_K : g_V);
        ccol = (nt & 7) * 128;
    } else {
        pA[0] = g_ah; pA[1] = g_ah; pA[2] = g_al;
        const __nv_bfloat16* bh = g_woh + (size_t)n0 * DM;
        const __nv_bfloat16* bl = g_wol + (size_t)n0 * DM;
        pB[0] = bh; pB[1] = bl; pB[2] = bh;
        C = outp; ccol = n0;
    }

    float acc[4][8][4];
#pragma unroll
    for (int a = 0; a < 4; a++)
#pragma unroll
        for (int b = 0; b < 8; b++)
#pragma unroll
            for (int c = 0; c < 4; c++) acc[a][b][c] = 0.f;

    // prologue: chunks 0,1
#pragma unroll
    for (int c = 0; c < 2; c++) {
        int pass = c >> 4, k0 = (c & 15) * 64;
        gemm_issue(t, sbase + (c & 1) * GSTAGE,
                   pA[pass] + (size_t)m0 * DM + k0, pB[pass] + k0);
    }

    const int wm = wid & 1, wn = wid >> 1;      // 2x2 warps, 64x64 each
    const int q = lane >> 3, r = lane & 7;

    for (int c = 0; c < 48; c++) {
        if (c + 1 < 48) { CP_WAIT1(); } else { CP_WAIT0(); }
        __syncthreads();

        const uint32_t sa = sbase + (c & 1) * GSTAGE + (wm * 64) * SKB;
        const uint32_t sb = sbase + (c & 1) * GSTAGE + GTILE + (wn * 64) * SKB;
#pragma unroll
        for (int ks = 0; ks < 4; ks++) {
            uint32_t af[4][4], bf[4][4];
#pragma unroll
            for (int mb = 0; mb < 4; mb++)
                ldsm_x4(af[mb], sa + (mb * 16 + (q & 1) * 8 + r) * SKB
                                   + (ks * 16 + (q >> 1) * 8) * 2);
#pragma unroll
            for (int np = 0; np < 4; np++)
                ldsm_x4(bf[np], sb + (np * 16 + (q >> 1) * 8 + r) * SKB
                                   + (ks * 16 + (q & 1) * 8) * 2);
#pragma unroll
            for (int mb = 0; mb < 4; mb++)
#pragma unroll
                for (int np = 0; np < 4; np++) {
                    mma16816(acc[mb][np * 2],     af[mb], &bf[np][0]);
                    mma16816(acc[mb][np * 2 + 1], af[mb], &bf[np][2]);
                }
        }
        __syncthreads();
        if (c + 2 < 48) {
            int cn = c + 2, pass = cn >> 4, k0 = (cn & 15) * 64;
            gemm_issue(t, sbase + (cn & 1) * GSTAGE,
                       pA[pass] + (size_t)m0 * DM + k0, pB[pass] + k0);
        }
    }

    const int rr = lane >> 2, c2 = (lane & 3) * 2;
#pragma unroll
    for (int mb = 0; mb < 4; mb++) {
        int row0 = m0 + wm * 64 + mb * 16 + rr;
#pragma unroll
        for (int nb = 0; nb < 8; nb++) {
            int col = ccol + wn * 64 + nb * 8 + c2;
            *(float2*)&C[(size_t)row0 * DM + col]       = make_float2(acc[mb][nb][0], acc[mb][nb][1]);
            *(float2*)&C[(size_t)(row0 + 8) * DM + col] = make_float2(acc[mb][nb][2], acc[mb][nb][3]);
        }
    }
}

// ---------------- RoPE + bf16 split (Q scaled by 1/8) + V split ----------------
__global__ void rope_cvt_kernel() {
    __shared__ float cs[32], sn[32];
    const int s = blockIdx.x, t = threadIdx.x;
    if (t < 32) {
        double invf = pow(10000.0, -((double)(2 * t)) / 64.0);
        double si, co;
        sincos((double)s * invf, &si, &co);
        cs[t] = (float)co; sn[t] = (float)si;
    }
    __syncthreads();
    for (int p = t; p < 512; p += 256) {
        int hh = p >> 5, i = p & 31;
        int base = s * DM + hh * 64 + i;
        float c = cs[i], si = sn[i];
        float q1 = g_Q[base], q2 = g_Q[base + 32];
        float qa = (q1 * c - q2 * si) * 0.125f;
        float qb = (q2 * c + q1 * si) * 0.125f;
        __nv_bfloat16 h, l;
        split1(qa, h, l); g_qh[base] = h;      g_ql[base] = l;
        split1(qb, h, l); g_qh[base + 32] = h; g_ql[base + 32] = l;
        float k1 = g_K[base], k2 = g_K[base + 32];
        float ka = k1 * c - k2 * si;
        float kb = k2 * c + k1 * si;
        split1(ka, h, l); g_kh[base] = h;      g_kl[base] = l;
        split1(kb, h, l); g_kh[base + 32] = h; g_kl[base + 32] = l;
    }
    for (int i = t; i < DM; i += 256) {
        __nv_bfloat16 h, l;
        split1(g_V[s * DM + i], h, l);
        g_vh[s * DM + i] = h; g_vl[s * DM + i] = l;
    }
}

// ---------------- Flash attention: HMMA split-bf16, causal, online softmax ----
// CTA = (q-tile 128 rows, head). 256 thr / 8 warps; warp = 16 q-rows x full 64 kv.
#define F_QH  0
#define F_QL  18432
#define F_STG 36864            // stage s at F_STG + s*36864: Kh,Kl,Vh,Vl (9216 each)
#define F_T   9216
#define FLASH_SMEM (36864 + 2 * 36864)   // 110592

__device__ __forceinline__ void flash_issue_kv(int t, uint32_t stg, int kbase, int h) {
    const size_t rowoff = (size_t)kbase * DM + h * 64;
    const __nv_bfloat16* srcs[4] = {g_kh + rowoff, g_kl + rowoff, g_vh + rowoff, g_vl + rowoff};
#pragma unroll
    for (int i = 0; i < 8; i++) {
        int idx = t + i * 256;              // 0..2047
        int mat = idx >> 9;                 // 0..3
        int rem = idx & 511;
        int row = rem >> 3, ch = rem & 7;
        cp_async16(stg + mat * F_T + row * SKB + ch * 16,
                   (const char*)srcs[mat] + (size_t)row * (DM * 2) + ch * 16);
    }
    CP_COMMIT();
}

__global__ __launch_bounds__(256)
void flash_kernel() {
    extern __shared__ char dsm[];
    const uint32_t sbase = smem_u32(dsm);
    const int t = threadIdx.x, lane = t & 31, wid = t >> 5;
    const int h = blockIdx.y;
    const int qt = (int)gridDim.x - 1 - (int)blockIdx.x;   // heavy first
    const int qbase = qt * 128;
    const int ntiles = 2 * qt + 2;

    // Q loads (both hi/lo) + tile0, then tile1
    {
        const size_t rowoff = (size_t)qbase * DM + h * 64;
#pragma unroll
        for (int i = 0; i < 8; i++) {
            int idx = t + i * 256;           // 0..2047
            int mat = idx >> 10;             // 0..1 (qh, ql)
            int rem = idx & 1023;
            int row = rem >> 3, ch = rem & 7;
            const __nv_bfloat16* src = (mat == 0 ? g_qh : g_ql) + rowoff;
            cp_async16(sbase + mat * 18432 + row * SKB + ch * 16,
                       (const char*)src + (size_t)row * (DM * 2) + ch * 16);
        }
        flash_issue_kv(t, sbase + F_STG, 0, h);          // shares group with Q
        flash_issue_kv(t, sbase + F_STG + 36864, 64, h); // tile 1
    }

    CP_WAIT1();          // Q + tile0 ready
    __syncthreads();

    // preload Q fragments (persistent)
    const int q = lane >> 3, r = lane & 7;
    uint32_t qhf[4][4], qlf[4][4];
#pragma unroll
    for (int ks = 0; ks < 4; ks++) {
        uint32_t ro = (wid * 16 + (q & 1) * 8 + r) * SKB + (ks * 16 + (q >> 1) * 8) * 2;
        ldsm_x4(qhf[ks], sbase + F_QH + ro);
        ldsm_x4(qlf[ks], sbase + F_QL + ro);
    }

    float o[8][4];
#pragma unroll
    for (int a = 0; a < 8; a++)
#pragma unroll
        for (int b = 0; b < 4; b++) o[a][b] = 0.f;
    float m0r = -1e30f, m1r = -1e30f, l0 = 0.f, l1 = 0.f;

    const int rr = lane >> 2, c2 = (lane & 3) * 2;
    const int qlo = qbase + wid * 16;
    const int qr0 = qlo + rr, qr1 = qr0 + 8;

    for (int kt = 0; kt < ntiles; kt++) {
        // NOTE: data for tile kt already waited on (prologue or end of prev iter)
        const uint32_t stg = sbase + F_STG + (kt & 1) * 36864;

        if (kt * 64 <= qlo + 15) {     // warp tile not fully masked
            float s[8][4];
#pragma unroll
            for (int a = 0; a < 8; a++)
#pragma unroll
                for (int b = 0; b < 4; b++) s[a][b] = 0.f;

            // S = Qh*Kh + Ql*Kh + Qh*Kl
#pragma unroll
            for (int ks = 0; ks < 4; ks++) {
#pragma unroll
                for (int np = 0; np < 4; np++) {
                    uint32_t kf[4];
                    uint32_t ro = (np * 16 + (q >> 1) * 8 + r) * SKB + (ks * 16 + (q & 1) * 8) * 2;
                    ldsm_x4(kf, stg + 0 * F_T + ro);           // Kh
                    mma16816(s[np * 2],     qhf[ks], &kf[0]);
                    mma16816(s[np * 2 + 1], qhf[ks], &kf[2]);
                    mma16816(s[np * 2],     qlf[ks], &kf[0]);
                    mma16816(s[np * 2 + 1], qlf[ks], &kf[2]);
                    ldsm_x4(kf, stg + 1 * F_T + ro);           // Kl
                    mma16816(s[np * 2],     qhf[ks], &kf[0]);
                    mma16816(s[np * 2 + 1], qhf[ks], &kf[2]);
                }
            }

            // causal mask (diagonal-straddling tiles only)
            if (kt * 64 + 63 > qlo) {
#pragma unroll
                for (int nb = 0; nb < 8; nb++) {
                    int kc = kt * 64 + nb * 8 + c2;
                    if (kc     > qr0) s[nb][0] = -1e30f;
                    if (kc + 1 > qr0) s[nb][1] = -1e30f;
                    if (kc     > qr1) s[nb][2] = -1e30f;
                    if (kc + 1 > qr1) s[nb][3] = -1e30f;
                }
            }

            // online softmax (rows: slot0 = regs 0,1; slot1 = regs 2,3)
            float mx0 = -1e30f, mx1 = -1e30f;
#pragma unroll
            for (int nb = 0; nb < 8; nb++) {
                mx0 = fmaxf(mx0, fmaxf(s[nb][0], s[nb][1]));
                mx1 = fmaxf(mx1, fmaxf(s[nb][2], s[nb][3]));
            }
            mx0 = fmaxf(mx0, __shfl_xor_sync(0xffffffffu, mx0, 1));
            mx0 = fmaxf(mx0, __shfl_xor_sync(0xffffffffu, mx0, 2));
            mx1 = fmaxf(mx1, __shfl_xor_sync(0xffffffffu, mx1, 1));
            mx1 = fmaxf(mx1, __shfl_xor_sync(0xffffffffu, mx1, 2));
            float mn0 = fmaxf(m0r, mx0), mn1 = fmaxf(m1r, mx1);
            float al0 = __expf(m0r - mn0), al1 = __expf(m1r - mn1);
            float sum0 = 0.f, sum1 = 0.f;
#pragma unroll
            for (int nb = 0; nb < 8; nb++) {
                s[nb][0] = __expf(s[nb][0] - mn0); sum0 += s[nb][0];
                s[nb][1] = __expf(s[nb][1] - mn0); sum0 += s[nb][1];
                s[nb][2] = __expf(s[nb][2] - mn1); sum1 += s[nb][2];
                s[nb][3] = __expf(s[nb][3] - mn1); sum1 += s[nb][3];
            }
            sum0 += __shfl_xor_sync(0xffffffffu, sum0, 1);
            sum0 += __shfl_xor_sync(0xffffffffu, sum0, 2);
            sum1 += __shfl_xor_sync(0xffffffffu, sum1, 1);
            sum1 += __shfl_xor_sync(0xffffffffu, sum1, 2);
            l0 = l0 * al0 + sum0;  l1 = l1 * al1 + sum1;
            m0r = mn0;  m1r = mn1;
#pragma unroll
            for (int nb = 0; nb < 8; nb++) {
                o[nb][0] *= al0; o[nb][1] *= al0;
                o[nb][2] *= al1; o[nb][3] *= al1;
            }

            // PV: O += (Ph+Pl)*Vh + Ph*Vl
#pragma unroll
            for (int ks = 0; ks < 4; ks++) {
                uint32_t ph[4], pl[4];
#pragma unroll
                for (int half = 0; half < 2; half++) {
                    int nb = 2 * ks + half;
                    __nv_bfloat16 h0, e0, h1, e1, h2, e2, h3, e3;
                    split1(s[nb][0], h0, e0); split1(s[nb][1], h1, e1);
                    split1(s[nb][2], h2, e2); split1(s[nb][3], h3, e3);
                    ph[half * 2]     = pack2(h0, h1);
                    ph[half * 2 + 1] = pack2(h2, h3);
                    pl[half * 2]     = pack2(e0, e1);
                    pl[half * 2 + 1] = pack2(e2, e3);
                }
#pragma unroll
                for (int dp = 0; dp < 4; dp++) {
                    uint32_t vf[4];
                    uint32_t ro = (ks * 16 + (q & 1) * 8 + r) * SKB + (dp * 16 + (q >> 1) * 8) * 2;
                    ldsm_x4t(vf, stg + 2 * F_T + ro);          // Vh
                    mma16816(o[dp * 2],     ph, &vf[0]);
                    mma16816(o[dp * 2 + 1], ph, &vf[2]);
                    mma16816(o[dp * 2],     pl, &vf[0]);
                    mma16816(o[dp * 2 + 1], pl, &vf[2]);
                    ldsm_x4t(vf, stg + 3 * F_T + ro);          // Vl
                    mma16816(o[dp * 2],     ph, &vf[0]);
                    mma16816(o[dp * 2 + 1], ph, &vf[2]);
                }
            }
        }

        __syncthreads();          // done reading this stage
        if (kt + 2 < ntiles)
            flash_issue_kv(t, sbase + F_STG + (kt & 1) * 36864, (kt + 2) * 64, h);
        if (kt + 1 < ntiles) {
            if (kt + 2 < ntiles) { CP_WAIT1(); } else { CP_WAIT0(); }
            __syncthreads();      // tile kt+1 data visible to all
        }
    }

    // epilogue: normalize, split hi/lo, store bf16x2
    float inv0 = 1.f / l0, inv1 = 1.f / l1;
#pragma unroll
    for (int nb = 0; nb < 8; nb++) {
        int col = h * 64 + nb * 8 + c2;
        __nv_bfloat16 h0, e0, h1, e1;
        split1(o[nb][0] * inv0, h0, e0);
        split1(o[nb][1] * inv0, h1, e1);
        *(uint32_t*)&g_ah[(size_t)qr0 * DM + col] = pack2(h0, h1);
        *(uint32_t*)&g_al[(size_t)qr0 * DM + col] = pack2(e0, e1);
        split1(o[nb][2] * inv1, h0, e0);
        split1(o[nb][3] * inv1, h1, e1);
        *(uint32_t*)&g_ah[(size_t)qr1 * DM + col] = pack2(h0, h1);
        *(uint32_t*)&g_al[(size_t)qr1 * DM + col] = pack2(e0, e1);
    }
}

// ---------------- launch ----------------
extern "C" void kernel_launch(void* const* d_in, const int* in_sizes, int n_in,
                              void* d_out, int out_size) {
    const float* x  = (const float*)d_in[0];
    const float* Wq = (const float*)d_in[1];
    const float* Wk = (const float*)d_in[2];
    const float* Wv = (const float*)d_in[3];
    const float* Wo = (const float*)d_in[4];
    float* out = (float*)d_out;

    cudaFuncSetAttribute(mma_gemm_kernel, cudaFuncAttributeMaxDynamicSharedMemorySize, GEMM_SMEM);
    cudaFuncSetAttribute(flash_kernel,   cudaFuncAttributeMaxDynamicSharedMemorySize, FLASH_SMEM);

    cvt_kernel<<<SEQ * DM / 1024, 256>>>(x, 0);
    cvt_kernel<<<DM * DM / 1024, 256>>>(Wq, 1);
    cvt_kernel<<<DM * DM / 1024, 256>>>(Wk, 2);
    cvt_kernel<<<DM * DM / 1024, 256>>>(Wv, 3);
    cvt_kernel<<<DM * DM / 1024, 256>>>(Wo, 4);

    mma_gemm_kernel<<<dim3(3 * DM / 128, SEQ / 128), 128, GEMM_SMEM>>>(0, nullptr);

    rope_cvt_kernel<<<SEQ, 256>>>();

    flash_kernel<<<dim3(SEQ / 128, NH), 256, FLASH_SMEM>>>();

    mma_gemm_kernel<<<dim3(DM / 128, SEQ / 128), 128, GEMM_SMEM>>>(1, out);
}

// round 5
// speedup vs baseline: 1.0019x; 1.0019x over previous
#include <cuda_runtime.h>
#include <cuda_bf16.h>
#include <math.h>
#include <stdint.h>

// Problem constants
#define SEQ   4096
#define DM    1024
#define NH    16
#define DH    64

// ---------------- scratch (no allocations allowed) ----------------
__device__ float g_Q[SEQ * DM];
__device__ float g_K[SEQ * DM];
__device__ float g_V[SEQ * DM];

__device__ __nv_bfloat16 g_xh[SEQ * DM],  g_xl[SEQ * DM];
__device__ __nv_bfloat16 g_wh[3 * DM * DM], g_wl[3 * DM * DM];   // Wq,Wk,Wv stacked rows
__device__ __nv_bfloat16 g_woh[DM * DM],  g_wol[DM * DM];
__device__ __nv_bfloat16 g_qh[SEQ * DM],  g_ql[SEQ * DM];        // roped, pre-scaled 1/8
__device__ __nv_bfloat16 g_kh[SEQ * DM],  g_kl[SEQ * DM];
__device__ __nv_bfloat16 g_vh[SEQ * DM],  g_vl[SEQ * DM];
__device__ __nv_bfloat16 g_ah[SEQ * DM],  g_al[SEQ * DM];        // attention out split

// ---------------- low-level helpers ----------------
__device__ __forceinline__ uint32_t smem_u32(const void* p) {
    uint32_t a;
    asm("{ .reg .u64 t; cvta.to.shared.u64 t, %1; cvt.u32.u64 %0, t; }" : "=r"(a) : "l"(p));
    return a;
}
__device__ __forceinline__ void cp_async16(uint32_t sa, const void* ga) {
    asm volatile("cp.async.cg.shared.global [%0], [%1], 16;" :: "r"(sa), "l"(ga));
}
#define CP_COMMIT() asm volatile("cp.async.commit_group;" ::: "memory")
#define CP_WAIT1()  asm volatile("cp.async.wait_group 1;" ::: "memory")
#define CP_WAIT0()  asm volatile("cp.async.wait_group 0;" ::: "memory")

__device__ __forceinline__ void ldsm_x4(uint32_t* r, uint32_t addr) {
    asm volatile("ldmatrix.sync.aligned.m8n8.x4.shared.b16 {%0,%1,%2,%3}, [%4];"
        : "=r"(r[0]), "=r"(r[1]), "=r"(r[2]), "=r"(r[3]) : "r"(addr));
}
__device__ __forceinline__ void ldsm_x4t(uint32_t* r, uint32_t addr) {
    asm volatile("ldmatrix.sync.aligned.m8n8.x4.trans.shared.b16 {%0,%1,%2,%3}, [%4];"
        : "=r"(r[0]), "=r"(r[1]), "=r"(r[2]), "=r"(r[3]) : "r"(addr));
}
__device__ __forceinline__ void mma16816(float* d, const uint32_t* a, const uint32_t* b) {
    asm volatile("mma.sync.aligned.m16n8k16.row.col.f32.bf16.bf16.f32 "
        "{%0,%1,%2,%3}, {%4,%5,%6,%7}, {%8,%9}, {%0,%1,%2,%3};"
        : "+f"(d[0]), "+f"(d[1]), "+f"(d[2]), "+f"(d[3])
        : "r"(a[0]), "r"(a[1]), "r"(a[2]), "r"(a[3]), "r"(b[0]), "r"(b[1]));
}
__device__ __forceinline__ uint32_t pack2(__nv_bfloat16 a, __nv_bfloat16 b) {
    __nv_bfloat162 t; t.x = a; t.y = b;
    uint32_t u; memcpy(&u, &t, 4); return u;
}
__device__ __forceinline__ void split1(float v, __nv_bfloat16& h, __nv_bfloat16& l) {
    h = __float2bfloat16(v);
    l = __float2bfloat16(v - __bfloat162float(h));
}

// ---------------- hi/lo convert kernel (inputs) ----------------
__global__ void cvt_kernel(const float* __restrict__ src, int sel) {
    __nv_bfloat16 *hi, *lo;
    switch (sel) {
        case 0: hi = g_xh;               lo = g_xl;               break;
        case 1: hi = g_wh;               lo = g_wl;               break;
        case 2: hi = g_wh + DM * DM;     lo = g_wl + DM * DM;     break;
        case 3: hi = g_wh + 2 * DM * DM; lo = g_wl + 2 * DM * DM; break;
        default: hi = g_woh;             lo = g_wol;              break;
    }
    int i = (blockIdx.x * 256 + threadIdx.x) * 4;
    float4 v = *(const float4*)&src[i];
    __nv_bfloat16 h0, l0, h1, l1, h2, l2, h3, l3;
    split1(v.x, h0, l0); split1(v.y, h1, l1);
    split1(v.z, h2, l2); split1(v.w, h3, l3);
    *(uint32_t*)&hi[i]     = pack2(h0, h1);
    *(uint32_t*)&hi[i + 2] = pack2(h2, h3);
    *(uint32_t*)&lo[i]     = pack2(l0, l1);
    *(uint32_t*)&lo[i + 2] = pack2(l2, l3);
}

// ---------------- HMMA split-bf16 NT GEMM ----------------
// C[m,n] = sum_k A[m,k]*B[n,k]; BM=BN=128, BK=64, 128 threads, 4 warps of 64x64.
#define SKB 144                    // smem row stride bytes (72 bf16, conflict-free ldsm)
#define GTILE (128 * SKB)          // 18432 B per matrix tile
#define GSTAGE (2 * GTILE)         // A+B
#define GEMM_SMEM (2 * GSTAGE)     // double buffer: 73728

__device__ __forceinline__ void gemm_issue(int t, uint32_t st,
                                           const __nv_bfloat16* A, const __nv_bfloat16* B) {
#pragma unroll
    for (int i = 0; i < 8; i++) {
        int idx = t + i * 128;
        int row = idx >> 3, ch = idx & 7;
        cp_async16(st + row * SKB + ch * 16,
                   (const char*)A + (size_t)row * (DM * 2) + ch * 16);
        cp_async16(st + GTILE + row * SKB + ch * 16,
                   (const char*)B + (size_t)row * (DM * 2) + ch * 16);
    }
    CP_COMMIT();
}

__global__ __launch_bounds__(128)
void mma_gemm_kernel(int which, float* __restrict__ outp) {
    extern __shared__ char dsm[];
    const uint32_t sbase = smem_u32(dsm);
    const int t = threadIdx.x, lane = t & 31, wid = t >> 5;
    const int nt = blockIdx.x, mt = blockIdx.y;
    const int m0 = mt * 128, n0 = nt * 128;

    const __nv_bfloat16 *pA[3], *pB[3];
    float* C; int ccol;
    if (which == 0) {
        pA[0] = g_xh; pA[1] = g_xh; pA[2] = g_xl;
        const __nv_bfloat16* bh = g_wh + (size_t)n0 * DM;
        const __nv_bfloat16* bl = g_wl + (size_t)n0 * DM;
        pB[0] = bh; pB[1] = bl; pB[2] = bh;
        int mat = nt >> 3;
        C = (mat == 0) ? g_Q : (mat == 1 ? g_K : g_V);
        ccol = (nt & 7) * 128;
    } else {
        pA[0] = g_ah; pA[1] = g_ah; pA[2] = g_al;
        const __nv_bfloat16* bh = g_woh + (size_t)n0 * DM;
        const __nv_bfloat16* bl = g_wol + (size_t)n0 * DM;
        pB[0] = bh; pB[1] = bl; pB[2] = bh;
        C = outp; ccol = n0;
    }

    float acc[4][8][4];
#pragma unroll
    for (int a = 0; a < 4; a++)
#pragma unroll
        for (int b = 0; b < 8; b++)
#pragma unroll
            for (int c = 0; c < 4; c++) acc[a][b][c] = 0.f;

    // prologue: chunks 0,1
#pragma unroll
    for (int c = 0; c < 2; c++) {
        int pass = c >> 4, k0 = (c & 15) * 64;
        gemm_issue(t, sbase + (c & 1) * GSTAGE,
                   pA[pass] + (size_t)m0 * DM + k0, pB[pass] + k0);
    }

    const int wm = wid & 1, wn = wid >> 1;      // 2x2 warps, 64x64 each
    const int q = lane >> 3, r = lane & 7;

    for (int c = 0; c < 48; c++) {
        if (c + 1 < 48) { CP_WAIT1(); } else { CP_WAIT0(); }
        __syncthreads();

        const uint32_t sa = sbase + (c & 1) * GSTAGE + (wm * 64) * SKB;
        const uint32_t sb = sbase + (c & 1) * GSTAGE + GTILE + (wn * 64) * SKB;
#pragma unroll
        for (int ks = 0; ks < 4; ks++) {
            uint32_t af[4][4], bf[4][4];
#pragma unroll
            for (int mb = 0; mb < 4; mb++)
                ldsm_x4(af[mb], sa + (mb * 16 + (q & 1) * 8 + r) * SKB
                                   + (ks * 16 + (q >> 1) * 8) * 2);
#pragma unroll
            for (int np = 0; np < 4; np++)
                ldsm_x4(bf[np], sb + (np * 16 + (q >> 1) * 8 + r) * SKB
                                   + (ks * 16 + (q & 1) * 8) * 2);
#pragma unroll
            for (int mb = 0; mb < 4; mb++)
#pragma unroll
                for (int np = 0; np < 4; np++) {
                    mma16816(acc[mb][np * 2],     af[mb], &bf[np][0]);
                    mma16816(acc[mb][np * 2 + 1], af[mb], &bf[np][2]);
                }
        }
        __syncthreads();
        if (c + 2 < 48) {
            int cn = c + 2, pass = cn >> 4, k0 = (cn & 15) * 64;
            gemm_issue(t, sbase + (cn & 1) * GSTAGE,
                       pA[pass] + (size_t)m0 * DM + k0, pB[pass] + k0);
        }
    }

    const int rr = lane >> 2, c2 = (lane & 3) * 2;
#pragma unroll
    for (int mb = 0; mb < 4; mb++) {
        int row0 = m0 + wm * 64 + mb * 16 + rr;
#pragma unroll
        for (int nb = 0; nb < 8; nb++) {
            int col = ccol + wn * 64 + nb * 8 + c2;
            *(float2*)&C[(size_t)row0 * DM + col]       = make_float2(acc[mb][nb][0], acc[mb][nb][1]);
            *(float2*)&C[(size_t)(row0 + 8) * DM + col] = make_float2(acc[mb][nb][2], acc[mb][nb][3]);
        }
    }
}

// ---------------- RoPE + bf16 split (Q scaled by 1/8) + V split ----------------
__global__ void rope_cvt_kernel() {
    __shared__ float cs[32], sn[32];
    const int s = blockIdx.x, t = threadIdx.x;
    if (t < 32) {
        double invf = pow(10000.0, -((double)(2 * t)) / 64.0);
        double si, co;
        sincos((double)s * invf, &si, &co);
        cs[t] = (float)co; sn[t] = (float)si;
    }
    __syncthreads();
    for (int p = t; p < 512; p += 256) {
        int hh = p >> 5, i = p & 31;
        int base = s * DM + hh * 64 + i;
        float c = cs[i], si = sn[i];
        float q1 = g_Q[base], q2 = g_Q[base + 32];
        float qa = (q1 * c - q2 * si) * 0.125f;
        float qb = (q2 * c + q1 * si) * 0.125f;
        __nv_bfloat16 h, l;
        split1(qa, h, l); g_qh[base] = h;      g_ql[base] = l;
        split1(qb, h, l); g_qh[base + 32] = h; g_ql[base + 32] = l;
        float k1 = g_K[base], k2 = g_K[base + 32];
        float ka = k1 * c - k2 * si;
        float kb = k2 * c + k1 * si;
        split1(ka, h, l); g_kh[base] = h;      g_kl[base] = l;
        split1(kb, h, l); g_kh[base + 32] = h; g_kl[base + 32] = l;
    }
    for (int i = t; i < DM; i += 256) {
        __nv_bfloat16 h, l;
        split1(g_V[s * DM + i], h, l);
        g_vh[s * DM + i] = h; g_vl[s * DM + i] = l;
    }
}

// ---------------- Flash attention: HMMA split-bf16, causal, online softmax ----
// CTA = (q-tile 128 rows, head). 256 thr / 8 warps; warp = 16 q-rows x full 64 kv.
#define F_QH  0
#define F_QL  18432
#define F_STG 36864            // stage s at F_STG + s*36864: Kh,Kl,Vh,Vl (9216 each)
#define F_T   9216
#define FLASH_SMEM (36864 + 2 * 36864)   // 110592

__device__ __forceinline__ void flash_issue_kv(int t, uint32_t stg, int kbase, int h) {
    const size_t rowoff = (size_t)kbase * DM + h * 64;
    const __nv_bfloat16* srcs[4] = {g_kh + rowoff, g_kl + rowoff, g_vh + rowoff, g_vl + rowoff};
#pragma unroll
    for (int i = 0; i < 8; i++) {
        int idx = t + i * 256;              // 0..2047
        int mat = idx >> 9;                 // 0..3
        int rem = idx & 511;
        int row = rem >> 3, ch = rem & 7;
        cp_async16(stg + mat * F_T + row * SKB + ch * 16,
                   (const char*)srcs[mat] + (size_t)row * (DM * 2) + ch * 16);
    }
    CP_COMMIT();
}

__global__ __launch_bounds__(256)
void flash_kernel() {
    extern __shared__ char dsm[];
    const uint32_t sbase = smem_u32(dsm);
    const int t = threadIdx.x, lane = t & 31, wid = t >> 5;
    const int h = blockIdx.y;
    const int qt = (int)gridDim.x - 1 - (int)blockIdx.x;   // heavy first
    const int qbase = qt * 128;
    const int ntiles = 2 * qt + 2;

    // Q loads (both hi/lo) + tile0, then tile1
    {
        const size_t rowoff = (size_t)qbase * DM + h * 64;
#pragma unroll
        for (int i = 0; i < 8; i++) {
            int idx = t + i * 256;           // 0..2047
            int mat = idx >> 10;             // 0..1 (qh, ql)
            int rem = idx & 1023;
            int row = rem >> 3, ch = rem & 7;
            const __nv_bfloat16* src = (mat == 0 ? g_qh : g_ql) + rowoff;
            cp_async16(sbase + mat * 18432 + row * SKB + ch * 16,
                       (const char*)src + (size_t)row * (DM * 2) + ch * 16);
        }
        flash_issue_kv(t, sbase + F_STG, 0, h);          // shares group with Q
        flash_issue_kv(t, sbase + F_STG + 36864, 64, h); // tile 1
    }

    CP_WAIT1();          // Q + tile0 ready
    __syncthreads();

    // preload Q fragments (persistent)
    const int q = lane >> 3, r = lane & 7;
    uint32_t qhf[4][4], qlf[4][4];
#pragma unroll
    for (int ks = 0; ks < 4; ks++) {
        uint32_t ro = (wid * 16 + (q & 1) * 8 + r) * SKB + (ks * 16 + (q >> 1) * 8) * 2;
        ldsm_x4(qhf[ks], sbase + F_QH + ro);
        ldsm_x4(qlf[ks], sbase + F_QL + ro);
    }

    float o[8][4];
#pragma unroll
    for (int a = 0; a < 8; a++)
#pragma unroll
        for (int b = 0; b < 4; b++) o[a][b] = 0.f;
    float m0r = -1e30f, m1r = -1e30f, l0 = 0.f, l1 = 0.f;

    const int rr = lane >> 2, c2 = (lane & 3) * 2;
    const int qlo = qbase + wid * 16;
    const int qr0 = qlo + rr, qr1 = qr0 + 8;

    for (int kt = 0; kt < ntiles; kt++) {
        // NOTE: data for tile kt already waited on (prologue or end of prev iter)
        const uint32_t stg = sbase + F_STG + (kt & 1) * 36864;

        if (kt * 64 <= qlo + 15) {     // warp tile not fully masked
            float s[8][4];
#pragma unroll
            for (int a = 0; a < 8; a++)
#pragma unroll
                for (int b = 0; b < 4; b++) s[a][b] = 0.f;

            // S = Qh*Kh + Ql*Kh + Qh*Kl
#pragma unroll
            for (int ks = 0; ks < 4; ks++) {
#pragma unroll
                for (int np = 0; np < 4; np++) {
                    uint32_t kf[4];
                    uint32_t ro = (np * 16 + (q >> 1) * 8 + r) * SKB + (ks * 16 + (q & 1) * 8) * 2;
                    ldsm_x4(kf, stg + 0 * F_T + ro);           // Kh
                    mma16816(s[np * 2],     qhf[ks], &kf[0]);
                    mma16816(s[np * 2 + 1], qhf[ks], &kf[2]);
                    mma16816(s[np * 2],     qlf[ks], &kf[0]);
                    mma16816(s[np * 2 + 1], qlf[ks], &kf[2]);
                    ldsm_x4(kf, stg + 1 * F_T + ro);           // Kl
                    mma16816(s[np * 2],     qhf[ks], &kf[0]);
                    mma16816(s[np * 2 + 1], qhf[ks], &kf[2]);
                }
            }

            // causal mask (diagonal-straddling tiles only)
            if (kt * 64 + 63 > qlo) {
#pragma unroll
                for (int nb = 0; nb < 8; nb++) {
                    int kc = kt * 64 + nb * 8 + c2;
                    if (kc     > qr0) s[nb][0] = -1e30f;
                    if (kc + 1 > qr0) s[nb][1] = -1e30f;
                    if (kc     > qr1) s[nb][2] = -1e30f;
                    if (kc + 1 > qr1) s[nb][3] = -1e30f;
                }
            }

            // online softmax (rows: slot0 = regs 0,1; slot1 = regs 2,3)
            float mx0 = -1e30f, mx1 = -1e30f;
#pragma unroll
            for (int nb = 0; nb < 8; nb++) {
                mx0 = fmaxf(mx0, fmaxf(s[nb][0], s[nb][1]));
                mx1 = fmaxf(mx1, fmaxf(s[nb][2], s[nb][3]));
            }
            mx0 = fmaxf(mx0, __shfl_xor_sync(0xffffffffu, mx0, 1));
            mx0 = fmaxf(mx0, __shfl_xor_sync(0xffffffffu, mx0, 2));
            mx1 = fmaxf(mx1, __shfl_xor_sync(0xffffffffu, mx1, 1));
            mx1 = fmaxf(mx1, __shfl_xor_sync(0xffffffffu, mx1, 2));
            float mn0 = fmaxf(m0r, mx0), mn1 = fmaxf(m1r, mx1);
            float al0 = __expf(m0r - mn0), al1 = __expf(m1r - mn1);
            float sum0 = 0.f, sum1 = 0.f;
#pragma unroll
            for (int nb = 0; nb < 8; nb++) {
                s[nb][0] = __expf(s[nb][0] - mn0); sum0 += s[nb][0];
                s[nb][1] = __expf(s[nb][1] - mn0); sum0 += s[nb][1];
                s[nb][2] = __expf(s[nb][2] - mn1); sum1 += s[nb][2];
                s[nb][3] = __expf(s[nb][3] - mn1); sum1 += s[nb][3];
            }
            sum0 += __shfl_xor_sync(0xffffffffu, sum0, 1);
            sum0 += __shfl_xor_sync(0xffffffffu, sum0, 2);
            sum1 += __shfl_xor_sync(0xffffffffu, sum1, 1);
            sum1 += __shfl_xor_sync(0xffffffffu, sum1, 2);
            l0 = l0 * al0 + sum0;  l1 = l1 * al1 + sum1;
            m0r = mn0;  m1r = mn1;
#pragma unroll
            for (int nb = 0; nb < 8; nb++) {
                o[nb][0] *= al0; o[nb][1] *= al0;
                o[nb][2] *= al1; o[nb][3] *= al1;
            }

            // PV: O += (Ph+Pl)*Vh + Ph*Vl
#pragma unroll
            for (int ks = 0; ks < 4; ks++) {
                uint32_t ph[4], pl[4];
#pragma unroll
                for (int half = 0; half < 2; half++) {
                    int nb = 2 * ks + half;
                    __nv_bfloat16 h0, e0, h1, e1, h2, e2, h3, e3;
                    split1(s[nb][0], h0, e0); split1(s[nb][1], h1, e1);
                    split1(s[nb][2], h2, e2); split1(s[nb][3], h3, e3);
                    ph[half * 2]     = pack2(h0, h1);
                    ph[half * 2 + 1] = pack2(h2, h3);
                    pl[half * 2]     = pack2(e0, e1);
                    pl[half * 2 + 1] = pack2(e2, e3);
                }
#pragma unroll
                for (int dp = 0; dp < 4; dp++) {
                    uint32_t vf[4];
                    uint32_t ro = (ks * 16 + (q & 1) * 8 + r) * SKB + (dp * 16 + (q >> 1) * 8) * 2;
                    ldsm_x4t(vf, stg + 2 * F_T + ro);          // Vh
                    mma16816(o[dp * 2],     ph, &vf[0]);
                    mma16816(o[dp * 2 + 1], ph, &vf[2]);
                    mma16816(o[dp * 2],     pl, &vf[0]);
                    mma16816(o[dp * 2 + 1], pl, &vf[2]);
                    ldsm_x4t(vf, stg + 3 * F_T + ro);          // Vl
                    mma16816(o[dp * 2],     ph, &vf[0]);
                    mma16816(o[dp * 2 + 1], ph, &vf[2]);
                }
            }
        }

        __syncthreads();          // done reading this stage
        if (kt + 2 < ntiles)
            flash_issue_kv(t, sbase + F_STG + (kt & 1) * 36864, (kt + 2) * 64, h);
        if (kt + 1 < ntiles) {
            if (kt + 2 < ntiles) { CP_WAIT1(); } else { CP_WAIT0(); }
            __syncthreads();      // tile kt+1 data visible to all
        }
    }

    // epilogue: normalize, split hi/lo, store bf16x2
    float inv0 = 1.f / l0, inv1 = 1.f / l1;
#pragma unroll
    for (int nb = 0; nb < 8; nb++) {
        int col = h * 64 + nb * 8 + c2;
        __nv_bfloat16 h0, e0, h1, e1;
        split1(o[nb][0] * inv0, h0, e0);
        split1(o[nb][1] * inv0, h1, e1);
        *(uint32_t*)&g_ah[(size_t)qr0 * DM + col] = pack2(h0, h1);
        *(uint32_t*)&g_al[(size_t)qr0 * DM + col] = pack2(e0, e1);
        split1(o[nb][2] * inv1, h0, e0);
        split1(o[nb][3] * inv1, h1, e1);
        *(uint32_t*)&g_ah[(size_t)qr1 * DM + col] = pack2(h0, h1);
        *(uint32_t*)&g_al[(size_t)qr1 * DM + col] = pack2(e0, e1);
    }
}

// ---------------- launch ----------------
extern "C" void kernel_launch(void* const* d_in, const int* in_sizes, int n_in,
                              void* d_out, int out_size) {
    const float* x  = (const float*)d_in[0];
    const float* Wq = (const float*)d_in[1];
    const float* Wk = (const float*)d_in[2];
    const float* Wv = (const float*)d_in[3];
    const float* Wo = (const float*)d_in[4];
    float* out = (float*)d_out;

    cudaFuncSetAttribute(mma_gemm_kernel, cudaFuncAttributeMaxDynamicSharedMemorySize, GEMM_SMEM);
    cudaFuncSetAttribute(flash_kernel,   cudaFuncAttributeMaxDynamicSharedMemorySize, FLASH_SMEM);

    cvt_kernel<<<SEQ * DM / 1024, 256>>>(x, 0);
    cvt_kernel<<<DM * DM / 1024, 256>>>(Wq, 1);
    cvt_kernel<<<DM * DM / 1024, 256>>>(Wk, 2);
    cvt_kernel<<<DM * DM / 1024, 256>>>(Wv, 3);
    cvt_kernel<<<DM * DM / 1024, 256>>>(Wo, 4);

    mma_gemm_kernel<<<dim3(3 * DM / 128, SEQ / 128), 128, GEMM_SMEM>>>(0, nullptr);

    rope_cvt_kernel<<<SEQ, 256>>>();

    flash_kernel<<<dim3(SEQ / 128, NH), 256, FLASH_SMEM>>>();

    mma_gemm_kernel<<<dim3(DM / 128, SEQ / 128), 128, GEMM_SMEM>>>(1, out);
}

// round 6
// speedup vs baseline: 1.3091x; 1.3066x over previous
#include <cuda_runtime.h>
#include <cuda_bf16.h>
#include <cuda_fp16.h>
#include <math.h>
#include <stdint.h>

// Problem constants
#define SEQ   4096
#define DM    1024
#define NH    16
#define DH    64

// ---------------- scratch (no allocations allowed) ----------------
__device__ float g_Q[SEQ * DM];
__device__ float g_K[SEQ * DM];
__device__ float g_V[SEQ * DM];

__device__ __nv_bfloat16 g_xh[SEQ * DM],  g_xl[SEQ * DM];
__device__ __nv_bfloat16 g_wh[3 * DM * DM], g_wl[3 * DM * DM];   // Wq,Wk,Wv stacked rows
__device__ __nv_bfloat16 g_woh[DM * DM],  g_wol[DM * DM];
__device__ __nv_bfloat16 g_ah[SEQ * DM],  g_al[SEQ * DM];        // attention out split (bf16)

// flash operands: fp16
__device__ __half g_qh[SEQ * DM], g_ql[SEQ * DM];   // roped Q, pre-scaled 1/8, hi/lo
__device__ __half g_kh[SEQ * DM];                    // roped K, hi only
__device__ __half g_vh[SEQ * DM];                    // V, hi only

// ---------------- low-level helpers ----------------
__device__ __forceinline__ uint32_t smem_u32(const void* p) {
    uint32_t a;
    asm("{ .reg .u64 t; cvta.to.shared.u64 t, %1; cvt.u32.u64 %0, t; }" : "=r"(a) : "l"(p));
    return a;
}
__device__ __forceinline__ void cp_async16(uint32_t sa, const void* ga) {
    asm volatile("cp.async.cg.shared.global [%0], [%1], 16;" :: "r"(sa), "l"(ga));
}
#define CP_COMMIT() asm volatile("cp.async.commit_group;" ::: "memory")
#define CP_WAIT1()  asm volatile("cp.async.wait_group 1;" ::: "memory")
#define CP_WAIT0()  asm volatile("cp.async.wait_group 0;" ::: "memory")

__device__ __forceinline__ void ldsm_x4(uint32_t* r, uint32_t addr) {
    asm volatile("ldmatrix.sync.aligned.m8n8.x4.shared.b16 {%0,%1,%2,%3}, [%4];"
        : "=r"(r[0]), "=r"(r[1]), "=r"(r[2]), "=r"(r[3]) : "r"(addr));
}
__device__ __forceinline__ void ldsm_x4t(uint32_t* r, uint32_t addr) {
    asm volatile("ldmatrix.sync.aligned.m8n8.x4.trans.shared.b16 {%0,%1,%2,%3}, [%4];"
        : "=r"(r[0]), "=r"(r[1]), "=r"(r[2]), "=r"(r[3]) : "r"(addr));
}
// bf16 mma (GEMMs)
__device__ __forceinline__ void mma16816(float* d, const uint32_t* a, const uint32_t* b) {
    asm volatile("mma.sync.aligned.m16n8k16.row.col.f32.bf16.bf16.f32 "
        "{%0,%1,%2,%3}, {%4,%5,%6,%7}, {%8,%9}, {%0,%1,%2,%3};"
        : "+f"(d[0]), "+f"(d[1]), "+f"(d[2]), "+f"(d[3])
        : "r"(a[0]), "r"(a[1]), "r"(a[2]), "r"(a[3]), "r"(b[0]), "r"(b[1]));
}
// fp16 mma (flash)
__device__ __forceinline__ void mma16816h(float* d, const uint32_t* a, const uint32_t* b) {
    asm volatile("mma.sync.aligned.m16n8k16.row.col.f32.f16.f16.f32 "
        "{%0,%1,%2,%3}, {%4,%5,%6,%7}, {%8,%9}, {%0,%1,%2,%3};"
        : "+f"(d[0]), "+f"(d[1]), "+f"(d[2]), "+f"(d[3])
        : "r"(a[0]), "r"(a[1]), "r"(a[2]), "r"(a[3]), "r"(b[0]), "r"(b[1]));
}
__device__ __forceinline__ uint32_t pack2(__nv_bfloat16 a, __nv_bfloat16 b) {
    __nv_bfloat162 t; t.x = a; t.y = b;
    uint32_t u; memcpy(&u, &t, 4); return u;
}
__device__ __forceinline__ uint32_t pack2h(float a, float b) {
    __half2 t; t.x = __float2half_rn(a); t.y = __float2half_rn(b);
    uint32_t u; memcpy(&u, &t, 4); return u;
}
__device__ __forceinline__ void split1(float v, __nv_bfloat16& h, __nv_bfloat16& l) {
    h = __float2bfloat16(v);
    l = __float2bfloat16(v - __bfloat162float(h));
}

// ---------------- fused hi/lo convert kernel (all 5 inputs, one launch) ----
__global__ void cvt_all_kernel(const float* __restrict__ x,
                               const float* __restrict__ Wq,
                               const float* __restrict__ Wk,
                               const float* __restrict__ Wv,
                               const float* __restrict__ Wo) {
    int b = blockIdx.x;
    const float* src; __nv_bfloat16 *hi, *lo; int base;
    if (b < 4096)      { src = x;  hi = g_xh;               lo = g_xl;               base = b; }
    else if (b < 5120) { src = Wq; hi = g_wh;               lo = g_wl;               base = b - 4096; }
    else if (b < 6144) { src = Wk; hi = g_wh + DM * DM;     lo = g_wl + DM * DM;     base = b - 5120; }
    else if (b < 7168) { src = Wv; hi = g_wh + 2 * DM * DM; lo = g_wl + 2 * DM * DM; base = b - 6144; }
    else               { src = Wo; hi = g_woh;              lo = g_wol;              base = b - 7168; }
    int i = (base * 256 + threadIdx.x) * 4;
    float4 v = *(const float4*)&src[i];
    __nv_bfloat16 h0, l0, h1, l1, h2, l2, h3, l3;
    split1(v.x, h0, l0); split1(v.y, h1, l1);
    split1(v.z, h2, l2); split1(v.w, h3, l3);
    *(uint32_t*)&hi[i]     = pack2(h0, h1);
    *(uint32_t*)&hi[i + 2] = pack2(h2, h3);
    *(uint32_t*)&lo[i]     = pack2(l0, l1);
    *(uint32_t*)&lo[i + 2] = pack2(l2, l3);
}

// ---------------- HMMA split-bf16 NT GEMM ----------------
// C[m,n] = sum_k A[m,k]*B[n,k]; BM=BN=128, BK=64, 128 threads, 4 warps of 64x64.
#define SKB 144                    // smem row stride bytes (72 elems, conflict-free ldsm)
#define GTILE (128 * SKB)          // 18432 B per matrix tile
#define GSTAGE (2 * GTILE)         // A+B
#define GEMM_SMEM (2 * GSTAGE)     // double buffer: 73728

__device__ __forceinline__ void gemm_issue(int t, uint32_t st,
                                           const __nv_bfloat16* A, const __nv_bfloat16* B) {
#pragma unroll
    for (int i = 0; i < 8; i++) {
        int idx = t + i * 128;
        int row = idx >> 3, ch = idx & 7;
        cp_async16(st + row * SKB + ch * 16,
                   (const char*)A + (size_t)row * (DM * 2) + ch * 16);
        cp_async16(st + GTILE + row * SKB + ch * 16,
                   (const char*)B + (size_t)row * (DM * 2) + ch * 16);
    }
    CP_COMMIT();
}

__global__ __launch_bounds__(128)
void mma_gemm_kernel(int which, float* __restrict__ outp) {
    extern __shared__ char dsm[];
    const uint32_t sbase = smem_u32(dsm);
    const int t = threadIdx.x, lane = t & 31, wid = t >> 5;
    const int nt = blockIdx.x, mt = blockIdx.y;
    const int m0 = mt * 128, n0 = nt * 128;

    const __nv_bfloat16 *pA[3], *pB[3];
    float* C; int ccol;
    if (which == 0) {
        pA[0] = g_xh; pA[1] = g_xh; pA[2] = g_xl;
        const __nv_bfloat16* bh = g_wh + (size_t)n0 * DM;
        const __nv_bfloat16* bl = g_wl + (size_t)n0 * DM;
        pB[0] = bh; pB[1] = bl; pB[2] = bh;
        int mat = nt >> 3;
        C = (mat == 0) ? g_Q : (mat == 1 ? g_K : g_V);
        ccol = (nt & 7) * 128;
    } else {
        // proj: A = attention out (bf16 h/l), B = Wo (bf16 h/l); 3-pass exact
        pA[0] = g_ah; pA[1] = g_ah; pA[2] = g_al;
        const __nv_bfloat16* bh = g_woh + (size_t)n0 * DM;
        const __nv_bfloat16* bl = g_wol + (size_t)n0 * DM;
        pB[0] = bh; pB[1] = bl; pB[2] = bh;
        C = outp; ccol = n0;
    }

    float acc[4][8][4];
#pragma unroll
    for (int a = 0; a < 4; a++)
#pragma unroll
        for (int b = 0; b < 8; b++)
#pragma unroll
            for (int c = 0; c < 4; c++) acc[a][b][c] = 0.f;

#pragma unroll
    for (int c = 0; c < 2; c++) {
        int pass = c >> 4, k0 = (c & 15) * 64;
        gemm_issue(t, sbase + (c & 1) * GSTAGE,
                   pA[pass] + (size_t)m0 * DM + k0, pB[pass] + k0);
    }

    const int wm = wid & 1, wn = wid >> 1;      // 2x2 warps, 64x64 each
    const int q = lane >> 3, r = lane & 7;

    for (int c = 0; c < 48; c++) {
        if (c + 1 < 48) { CP_WAIT1(); } else { CP_WAIT0(); }
        __syncthreads();

        const uint32_t sa = sbase + (c & 1) * GSTAGE + (wm * 64) * SKB;
        const uint32_t sb = sbase + (c & 1) * GSTAGE + GTILE + (wn * 64) * SKB;
#pragma unroll
        for (int ks = 0; ks < 4; ks++) {
            uint32_t af[4][4], bf[4][4];
#pragma unroll
            for (int mb = 0; mb < 4; mb++)
                ldsm_x4(af[mb], sa + (mb * 16 + (q & 1) * 8 + r) * SKB
                                   + (ks * 16 + (q >> 1) * 8) * 2);
#pragma unroll
            for (int np = 0; np < 4; np++)
                ldsm_x4(bf[np], sb + (np * 16 + (q >> 1) * 8 + r) * SKB
                                   + (ks * 16 + (q & 1) * 8) * 2);
#pragma unroll
            for (int mb = 0; mb < 4; mb++)
#pragma unroll
                for (int np = 0; np < 4; np++) {
                    mma16816(acc[mb][np * 2],     af[mb], &bf[np][0]);
                    mma16816(acc[mb][np * 2 + 1], af[mb], &bf[np][2]);
                }
        }
        __syncthreads();
        if (c + 2 < 48) {
            int cn = c + 2, pass = cn >> 4, k0 = (cn & 15) * 64;
            gemm_issue(t, sbase + (cn & 1) * GSTAGE,
                       pA[pass] + (size_t)m0 * DM + k0, pB[pass] + k0);
        }
    }

    const int rr = lane >> 2, c2 = (lane & 3) * 2;
#pragma unroll
    for (int mb = 0; mb < 4; mb++) {
        int row0 = m0 + wm * 64 + mb * 16 + rr;
#pragma unroll
        for (int nb = 0; nb < 8; nb++) {
            int col = ccol + wn * 64 + nb * 8 + c2;
            *(float2*)&C[(size_t)row0 * DM + col]       = make_float2(acc[mb][nb][0], acc[mb][nb][1]);
            *(float2*)&C[(size_t)(row0 + 8) * DM + col] = make_float2(acc[mb][nb][2], acc[mb][nb][3]);
        }
    }
}

// ---------------- RoPE + fp16 convert (Q hi/lo scaled 1/8; K, V hi only) ----
__global__ void rope_cvt_kernel() {
    __shared__ float cs[32], sn[32];
    const int s = blockIdx.x, t = threadIdx.x;
    if (t < 32) {
        double invf = pow(10000.0, -((double)(2 * t)) / 64.0);
        double si, co;
        sincos((double)s * invf, &si, &co);
        cs[t] = (float)co; sn[t] = (float)si;
    }
    __syncthreads();
    for (int p = t; p < 512; p += 256) {
        int hh = p >> 5, i = p & 31;
        int base = s * DM + hh * 64 + i;
        float c = cs[i], si = sn[i];
        float q1 = g_Q[base], q2 = g_Q[base + 32];
        float qa = (q1 * c - q2 * si) * 0.125f;
        float qb = (q2 * c + q1 * si) * 0.125f;
        __half qah = __float2half_rn(qa);
        __half qbh = __float2half_rn(qb);
        g_qh[base]      = qah; g_ql[base]      = __float2half_rn(qa - __half2float(qah));
        g_qh[base + 32] = qbh; g_ql[base + 32] = __float2half_rn(qb - __half2float(qbh));
        float k1 = g_K[base], k2 = g_K[base + 32];
        g_kh[base]      = __float2half_rn(k1 * c - k2 * si);
        g_kh[base + 32] = __float2half_rn(k2 * c + k1 * si);
    }
    for (int i = t; i < DM; i += 256) {
        g_vh[s * DM + i] = __float2half_rn(g_V[s * DM + i]);
    }
}

// ---------------- Flash attention: fp16 HMMA, S 2-pass, PV 1-pass -----------
// CTA = (q-tile 128 rows, head). 256 thr / 8 warps; warp = 16 q-rows x full 64 kv.
#define F_QH  0
#define F_QL  18432
#define F_STG 36864            // stage s at F_STG + s*F_STGSZ: Kh, Vh (9216 each)
#define F_T   9216
#define F_STGSZ 18432
#define FLASH_SMEM (36864 + 2 * F_STGSZ)   // 73728 -> 2 CTAs/SM possible

__device__ __forceinline__ void flash_issue_kv(int t, uint32_t stg, int kbase, int h) {
    const size_t rowoff = (size_t)kbase * DM + h * 64;
    const __half* srcs[2] = {g_kh + rowoff, g_vh + rowoff};
#pragma unroll
    for (int i = 0; i < 4; i++) {
        int idx = t + i * 256;              // 0..1023
        int mat = idx >> 9;                 // 0..1
        int rem = idx & 511;
        int row = rem >> 3, ch = rem & 7;
        cp_async16(stg + mat * F_T + row * SKB + ch * 16,
                   (const char*)srcs[mat] + (size_t)row * (DM * 2) + ch * 16);
    }
    CP_COMMIT();
}

__global__ __launch_bounds__(256)
void flash_kernel() {
    extern __shared__ char dsm[];
    const uint32_t sbase = smem_u32(dsm);
    const int t = threadIdx.x, lane = t & 31, wid = t >> 5;
    const int h = blockIdx.y;
    const int qt = (int)gridDim.x - 1 - (int)blockIdx.x;   // heavy first
    const int qbase = qt * 128;
    const int ntiles = 2 * qt + 2;

    // Q hi/lo loads + kv tile0, then kv tile1
    {
        const size_t rowoff = (size_t)qbase * DM + h * 64;
#pragma unroll
        for (int i = 0; i < 8; i++) {
            int idx = t + i * 256;           // 0..2047
            int mat = idx >> 10;             // 0..1 (qh, ql)
            int rem = idx & 1023;
            int row = rem >> 3, ch = rem & 7;
            const __half* src = (mat == 0 ? g_qh : g_ql) + rowoff;
            cp_async16(sbase + mat * 18432 + row * SKB + ch * 16,
                       (const char*)src + (size_t)row * (DM * 2) + ch * 16);
        }
        flash_issue_kv(t, sbase + F_STG, 0, h);            // shares group with Q
        flash_issue_kv(t, sbase + F_STG + F_STGSZ, 64, h); // tile 1
    }

    CP_WAIT1();          // Q + tile0 ready
    __syncthreads();

    // preload Q fragments (persistent)
    const int q = lane >> 3, r = lane & 7;
    uint32_t qhf[4][4], qlf[4][4];
#pragma unroll
    for (int ks = 0; ks < 4; ks++) {
        uint32_t ro = (wid * 16 + (q & 1) * 8 + r) * SKB + (ks * 16 + (q >> 1) * 8) * 2;
        ldsm_x4(qhf[ks], sbase + F_QH + ro);
        ldsm_x4(qlf[ks], sbase + F_QL + ro);
    }

    float o[8][4];
#pragma unroll
    for (int a = 0; a < 8; a++)
#pragma unroll
        for (int b = 0; b < 4; b++) o[a][b] = 0.f;
    float m0r = -1e30f, m1r = -1e30f, l0 = 0.f, l1 = 0.f;

    const int rr = lane >> 2, c2 = (lane & 3) * 2;
    const int qlo = qbase + wid * 16;
    const int qr0 = qlo + rr, qr1 = qr0 + 8;

    for (int kt = 0; kt < ntiles; kt++) {
        const uint32_t stg = sbase + F_STG + (kt & 1) * F_STGSZ;

        if (kt * 64 <= qlo + 15) {     // warp tile not fully masked
            float s[8][4];
#pragma unroll
            for (int a = 0; a < 8; a++)
#pragma unroll
                for (int b = 0; b < 4; b++) s[a][b] = 0.f;

            // S = (Qh + Ql) * Kh  (2-pass)
#pragma unroll
            for (int ks = 0; ks < 4; ks++) {
#pragma unroll
                for (int np = 0; np < 4; np++) {
                    uint32_t kf[4];
                    uint32_t ro = (np * 16 + (q >> 1) * 8 + r) * SKB + (ks * 16 + (q & 1) * 8) * 2;
                    ldsm_x4(kf, stg + 0 * F_T + ro);           // Kh
                    mma16816h(s[np * 2],     qhf[ks], &kf[0]);
                    mma16816h(s[np * 2 + 1], qhf[ks], &kf[2]);
                    mma16816h(s[np * 2],     qlf[ks], &kf[0]);
                    mma16816h(s[np * 2 + 1], qlf[ks], &kf[2]);
                }
            }

            // causal mask (diagonal-straddling tiles only)
            if (kt * 64 + 63 > qlo) {
#pragma unroll
                for (int nb = 0; nb < 8; nb++) {
                    int kc = kt * 64 + nb * 8 + c2;
                    if (kc     > qr0) s[nb][0] = -1e30f;
                    if (kc + 1 > qr0) s[nb][1] = -1e30f;
                    if (kc     > qr1) s[nb][2] = -1e30f;
                    if (kc + 1 > qr1) s[nb][3] = -1e30f;
                }
            }

            // online softmax
            float mx0 = -1e30f, mx1 = -1e30f;
#pragma unroll
            for (int nb = 0; nb < 8; nb++) {
                mx0 = fmaxf(mx0, fmaxf(s[nb][0], s[nb][1]));
                mx1 = fmaxf(mx1, fmaxf(s[nb][2], s[nb][3]));
            }
            mx0 = fmaxf(mx0, __shfl_xor_sync(0xffffffffu, mx0, 1));
            mx0 = fmaxf(mx0, __shfl_xor_sync(0xffffffffu, mx0, 2));
            mx1 = fmaxf(mx1, __shfl_xor_sync(0xffffffffu, mx1, 1));
            mx1 = fmaxf(mx1, __shfl_xor_sync(0xffffffffu, mx1, 2));
            float mn0 = fmaxf(m0r, mx0), mn1 = fmaxf(m1r, mx1);
            float al0 = __expf(m0r - mn0), al1 = __expf(m1r - mn1);
            float sum0 = 0.f, sum1 = 0.f;
#pragma unroll
            for (int nb = 0; nb < 8; nb++) {
                s[nb][0] = __expf(s[nb][0] - mn0); sum0 += s[nb][0];
                s[nb][1] = __expf(s[nb][1] - mn0); sum0 += s[nb][1];
                s[nb][2] = __expf(s[nb][2] - mn1); sum1 += s[nb][2];
                s[nb][3] = __expf(s[nb][3] - mn1); sum1 += s[nb][3];
            }
            sum0 += __shfl_xor_sync(0xffffffffu, sum0, 1);
            sum0 += __shfl_xor_sync(0xffffffffu, sum0, 2);
            sum1 += __shfl_xor_sync(0xffffffffu, sum1, 1);
            sum1 += __shfl_xor_sync(0xffffffffu, sum1, 2);
            l0 = l0 * al0 + sum0;  l1 = l1 * al1 + sum1;
            m0r = mn0;  m1r = mn1;
#pragma unroll
            for (int nb = 0; nb < 8; nb++) {
                o[nb][0] *= al0; o[nb][1] *= al0;
                o[nb][2] *= al1; o[nb][3] *= al1;
            }

            // PV: O += P * Vh (1-pass, P rounded to fp16)
#pragma unroll
            for (int ks = 0; ks < 4; ks++) {
                uint32_t ph[4];
#pragma unroll
                for (int half = 0; half < 2; half++) {
                    int nb = 2 * ks + half;
                    ph[half * 2]     = pack2h(s[nb][0], s[nb][1]);
                    ph[half * 2 + 1] = pack2h(s[nb][2], s[nb][3]);
                }
#pragma unroll
                for (int dp = 0; dp < 4; dp++) {
                    uint32_t vf[4];
                    uint32_t ro = (ks * 16 + (q & 1) * 8 + r) * SKB + (dp * 16 + (q >> 1) * 8) * 2;
                    ldsm_x4t(vf, stg + 1 * F_T + ro);          // Vh
                    mma16816h(o[dp * 2],     ph, &vf[0]);
                    mma16816h(o[dp * 2 + 1], ph, &vf[2]);
                }
            }
        }

        __syncthreads();          // done reading this stage
        if (kt + 2 < ntiles)
            flash_issue_kv(t, sbase + F_STG + (kt & 1) * F_STGSZ, (kt + 2) * 64, h);
        if (kt + 1 < ntiles) {
            if (kt + 2 < ntiles) { CP_WAIT1(); } else { CP_WAIT0(); }
            __syncthreads();      // tile kt+1 data visible to all
        }
    }

    // epilogue: normalize, split hi/lo, store bf16x2 (exact input to 3-pass proj)
    float inv0 = 1.f / l0, inv1 = 1.f / l1;
#pragma unroll
    for (int nb = 0; nb < 8; nb++) {
        int col = h * 64 + nb * 8 + c2;
        __nv_bfloat16 h0, e0, h1, e1;
        split1(o[nb][0] * inv0, h0, e0);
        split1(o[nb][1] * inv0, h1, e1);
        *(uint32_t*)&g_ah[(size_t)qr0 * DM + col] = pack2(h0, h1);
        *(uint32_t*)&g_al[(size_t)qr0 * DM + col] = pack2(e0, e1);
        split1(o[nb][2] * inv1, h0, e0);
        split1(o[nb][3] * inv1, h1, e1);
        *(uint32_t*)&g_ah[(size_t)qr1 * DM + col] = pack2(h0, h1);
        *(uint32_t*)&g_al[(size_t)qr1 * DM + col] = pack2(e0, e1);
    }
}

// ---------------- launch ----------------
extern "C" void kernel_launch(void* const* d_in, const int* in_sizes, int n_in,
                              void* d_out, int out_size) {
    const float* x  = (const float*)d_in[0];
    const float* Wq = (const float*)d_in[1];
    const float* Wk = (const float*)d_in[2];
    const float* Wv = (const float*)d_in[3];
    const float* Wo = (const float*)d_in[4];
    float* out = (float*)d_out;

    cudaFuncSetAttribute(mma_gemm_kernel, cudaFuncAttributeMaxDynamicSharedMemorySize, GEMM_SMEM);
    cudaFuncSetAttribute(flash_kernel,   cudaFuncAttributeMaxDynamicSharedMemorySize, FLASH_SMEM);

    cvt_all_kernel<<<8192, 256>>>(x, Wq, Wk, Wv, Wo);

    mma_gemm_kernel<<<dim3(3 * DM / 128, SEQ / 128), 128, GEMM_SMEM>>>(0, nullptr);

    rope_cvt_kernel<<<SEQ, 256>>>();

    flash_kernel<<<dim3(SEQ / 128, NH), 256, FLASH_SMEM>>>();

    mma_gemm_kernel<<<dim3(DM / 128, SEQ / 128), 128, GEMM_SMEM>>>(1, out);
}

// round 7
// speedup vs baseline: 1.6552x; 1.2644x over previous
#include <cuda_runtime.h>
#include <cuda_bf16.h>
#include <cuda_fp16.h>
#include <math.h>
#include <stdint.h>

// Problem constants
#define SEQ   4096
#define DM    1024
#define NH    16
#define DH    64

// ---------------- scratch (no allocations allowed) ----------------
__device__ float g_Q[SEQ * DM];
__device__ float g_K[SEQ * DM];
__device__ float g_V[SEQ * DM];

// QKV GEMM operands (fp16): x hi/lo, W hi only (Wq,Wk,Wv stacked rows)
__device__ __half g_x16h[SEQ * DM], g_x16l[SEQ * DM];
__device__ __half g_w16[3 * DM * DM];
// proj GEMM operands (bf16, exact 3-pass)
__device__ __nv_bfloat16 g_woh[DM * DM], g_wol[DM * DM];
__device__ __nv_bfloat16 g_ah[SEQ * DM], g_al[SEQ * DM];   // attention out split

// flash operands (fp16)
__device__ __half g_qh[SEQ * DM];   // roped Q, pre-scaled 1/8, hi only
__device__ __half g_kh[SEQ * DM];   // roped K, hi only
__device__ __half g_vh[SEQ * DM];   // V, hi only

// ---------------- low-level helpers ----------------
__device__ __forceinline__ uint32_t smem_u32(const void* p) {
    uint32_t a;
    asm("{ .reg .u64 t; cvta.to.shared.u64 t, %1; cvt.u32.u64 %0, t; }" : "=r"(a) : "l"(p));
    return a;
}
__device__ __forceinline__ void cp_async16(uint32_t sa, const void* ga) {
    asm volatile("cp.async.cg.shared.global [%0], [%1], 16;" :: "r"(sa), "l"(ga));
}
#define CP_COMMIT() asm volatile("cp.async.commit_group;" ::: "memory")
#define CP_WAIT1()  asm volatile("cp.async.wait_group 1;" ::: "memory")
#define CP_WAIT0()  asm volatile("cp.async.wait_group 0;" ::: "memory")

__device__ __forceinline__ void ldsm_x4(uint32_t* r, uint32_t addr) {
    asm volatile("ldmatrix.sync.aligned.m8n8.x4.shared.b16 {%0,%1,%2,%3}, [%4];"
        : "=r"(r[0]), "=r"(r[1]), "=r"(r[2]), "=r"(r[3]) : "r"(addr));
}
__device__ __forceinline__ void ldsm_x4t(uint32_t* r, uint32_t addr) {
    asm volatile("ldmatrix.sync.aligned.m8n8.x4.trans.shared.b16 {%0,%1,%2,%3}, [%4];"
        : "=r"(r[0]), "=r"(r[1]), "=r"(r[2]), "=r"(r[3]) : "r"(addr));
}
// bf16 mma
__device__ __forceinline__ void mma16816(float* d, const uint32_t* a, const uint32_t* b) {
    asm volatile("mma.sync.aligned.m16n8k16.row.col.f32.bf16.bf16.f32 "
        "{%0,%1,%2,%3}, {%4,%5,%6,%7}, {%8,%9}, {%0,%1,%2,%3};"
        : "+f"(d[0]), "+f"(d[1]), "+f"(d[2]), "+f"(d[3])
        : "r"(a[0]), "r"(a[1]), "r"(a[2]), "r"(a[3]), "r"(b[0]), "r"(b[1]));
}
// fp16 mma
__device__ __forceinline__ void mma16816h(float* d, const uint32_t* a, const uint32_t* b) {
    asm volatile("mma.sync.aligned.m16n8k16.row.col.f32.f16.f16.f32 "
        "{%0,%1,%2,%3}, {%4,%5,%6,%7}, {%8,%9}, {%0,%1,%2,%3};"
        : "+f"(d[0]), "+f"(d[1]), "+f"(d[2]), "+f"(d[3])
        : "r"(a[0]), "r"(a[1]), "r"(a[2]), "r"(a[3]), "r"(b[0]), "r"(b[1]));
}
__device__ __forceinline__ uint32_t pack2(__nv_bfloat16 a, __nv_bfloat16 b) {
    __nv_bfloat162 t; t.x = a; t.y = b;
    uint32_t u; memcpy(&u, &t, 4); return u;
}
__device__ __forceinline__ uint32_t pack2h(float a, float b) {
    __half2 t; t.x = __float2half_rn(a); t.y = __float2half_rn(b);
    uint32_t u; memcpy(&u, &t, 4); return u;
}
__device__ __forceinline__ void split1(float v, __nv_bfloat16& h, __nv_bfloat16& l) {
    h = __float2bfloat16(v);
    l = __float2bfloat16(v - __bfloat162float(h));
}
__device__ __forceinline__ void split1h(float v, __half& h, __half& l) {
    h = __float2half_rn(v);
    l = __float2half_rn(v - __half2float(h));
}

// ---------------- fused convert kernel (all 5 inputs, one launch) ----------
// b in [0,4096): x -> fp16 hi/lo
// b in [4096,7168): Wq/Wk/Wv -> fp16 hi (stacked)
// b in [7168,8192): Wo -> bf16 hi/lo
__global__ void cvt_all_kernel(const float* __restrict__ x,
                               const float* __restrict__ Wq,
                               const float* __restrict__ Wk,
                               const float* __restrict__ Wv,
                               const float* __restrict__ Wo) {
    int b = blockIdx.x;
    if (b < 4096) {
        int i = (b * 256 + threadIdx.x) * 4;
        float4 v = *(const float4*)&x[i];
        __half h0, l0, h1, l1, h2, l2, h3, l3;
        split1h(v.x, h0, l0); split1h(v.y, h1, l1);
        split1h(v.z, h2, l2); split1h(v.w, h3, l3);
        __half2 a; uint32_t u;
        a.x = h0; a.y = h1; memcpy(&u, &a, 4); *(uint32_t*)&g_x16h[i]     = u;
        a.x = h2; a.y = h3; memcpy(&u, &a, 4); *(uint32_t*)&g_x16h[i + 2] = u;
        a.x = l0; a.y = l1; memcpy(&u, &a, 4); *(uint32_t*)&g_x16l[i]     = u;
        a.x = l2; a.y = l3; memcpy(&u, &a, 4); *(uint32_t*)&g_x16l[i + 2] = u;
    } else if (b < 7168) {
        int bb = b - 4096;                 // 0..3071
        int mat = bb >> 10;                // 0..2
        const float* src = (mat == 0) ? Wq : (mat == 1 ? Wk : Wv);
        int si = ((bb & 1023) * 256 + threadIdx.x) * 4;
        int di = (bb * 256 + threadIdx.x) * 4;
        float4 v = *(const float4*)&src[si];
        __half2 a; uint32_t u;
        a.x = __float2half_rn(v.x); a.y = __float2half_rn(v.y);
        memcpy(&u, &a, 4); *(uint32_t*)&g_w16[di] = u;
        a.x = __float2half_rn(v.z); a.y = __float2half_rn(v.w);
        memcpy(&u, &a, 4); *(uint32_t*)&g_w16[di + 2] = u;
    } else {
        int i = ((b - 7168) * 256 + threadIdx.x) * 4;
        float4 v = *(const float4*)&Wo[i];
        __nv_bfloat16 h0, l0, h1, l1, h2, l2, h3, l3;
        split1(v.x, h0, l0); split1(v.y, h1, l1);
        split1(v.z, h2, l2); split1(v.w, h3, l3);
        *(uint32_t*)&g_woh[i]     = pack2(h0, h1);
        *(uint32_t*)&g_woh[i + 2] = pack2(h2, h3);
        *(uint32_t*)&g_wol[i]     = pack2(l0, l1);
        *(uint32_t*)&g_wol[i + 2] = pack2(l2, l3);
    }
}

// ---------------- HMMA NT GEMM (templated on pass structure/dtype) ----------
// C[m,n] = sum_k A[m,k]*B[n,k]; BM=BN=128, BK=64, 128 threads, 4 warps of 64x64.
// WHICH=0: QKV, fp16 2-pass (AhBh + AlBh). WHICH=1: proj, bf16 3-pass (exact).
#define SKB 144                    // smem row stride bytes (72 elems, conflict-free ldsm)
#define GTILE (128 * SKB)          // 18432 B per matrix tile
#define GSTAGE (2 * GTILE)         // A+B
#define GEMM_SMEM (2 * GSTAGE)     // double buffer: 73728

__device__ __forceinline__ void gemm_issue(int t, uint32_t st,
                                           const char* A, const char* B) {
#pragma unroll
    for (int i = 0; i < 8; i++) {
        int idx = t + i * 128;
        int row = idx >> 3, ch = idx & 7;
        cp_async16(st + row * SKB + ch * 16, A + (size_t)row * (DM * 2) + ch * 16);
        cp_async16(st + GTILE + row * SKB + ch * 16, B + (size_t)row * (DM * 2) + ch * 16);
    }
    CP_COMMIT();
}

template<int WHICH>
__global__ __launch_bounds__(128)
void mma_gemm_kernel(float* __restrict__ outp) {
    constexpr int NPASS = (WHICH == 0) ? 2 : 3;
    constexpr int NCH = NPASS * 16;
    extern __shared__ char dsm[];
    const uint32_t sbase = smem_u32(dsm);
    const int t = threadIdx.x, lane = t & 31, wid = t >> 5;
    const int nt = blockIdx.x, mt = blockIdx.y;
    const int m0 = mt * 128, n0 = nt * 128;

    const char *pA[3], *pB[3];
    float* C; int ccol;
    if (WHICH == 0) {
        pA[0] = (const char*)g_x16h; pA[1] = (const char*)g_x16l; pA[2] = nullptr;
        const char* bh = (const char*)(g_w16 + (size_t)n0 * DM);
        pB[0] = bh; pB[1] = bh; pB[2] = nullptr;
        int mat = nt >> 3;
        C = (mat == 0) ? g_Q : (mat == 1 ? g_K : g_V);
        ccol = (nt & 7) * 128;
    } else {
        pA[0] = (const char*)g_ah; pA[1] = (const char*)g_ah; pA[2] = (const char*)g_al;
        const char* bh = (const char*)(g_woh + (size_t)n0 * DM);
        const char* bl = (const char*)(g_wol + (size_t)n0 * DM);
        pB[0] = bh; pB[1] = bl; pB[2] = bh;
        C = outp; ccol = n0;
    }

    float acc[4][8][4];
#pragma unroll
    for (int a = 0; a < 4; a++)
#pragma unroll
        for (int b = 0; b < 8; b++)
#pragma unroll
            for (int c = 0; c < 4; c++) acc[a][b][c] = 0.f;

#pragma unroll
    for (int c = 0; c < 2; c++) {
        int pass = c >> 4, k0 = (c & 15) * 64;
        gemm_issue(t, sbase + (c & 1) * GSTAGE,
                   pA[pass] + (size_t)m0 * (DM * 2) + k0 * 2, pB[pass] + k0 * 2);
    }

    const int wm = wid & 1, wn = wid >> 1;      // 2x2 warps, 64x64 each
    const int q = lane >> 3, r = lane & 7;

    for (int c = 0; c < NCH; c++) {
        if (c + 1 < NCH) { CP_WAIT1(); } else { CP_WAIT0(); }
        __syncthreads();

        const uint32_t sa = sbase + (c & 1) * GSTAGE + (wm * 64) * SKB;
        const uint32_t sb = sbase + (c & 1) * GSTAGE + GTILE + (wn * 64) * SKB;
#pragma unroll
        for (int ks = 0; ks < 4; ks++) {
            uint32_t af[4][4], bf[4][4];
#pragma unroll
            for (int mb = 0; mb < 4; mb++)
                ldsm_x4(af[mb], sa + (mb * 16 + (q & 1) * 8 + r) * SKB
                                   + (ks * 16 + (q >> 1) * 8) * 2);
#pragma unroll
            for (int np = 0; np < 4; np++)
                ldsm_x4(bf[np], sb + (np * 16 + (q >> 1) * 8 + r) * SKB
                                   + (ks * 16 + (q & 1) * 8) * 2);
#pragma unroll
            for (int mb = 0; mb < 4; mb++)
#pragma unroll
                for (int np = 0; np < 4; np++) {
                    if (WHICH == 0) {
                        mma16816h(acc[mb][np * 2],     af[mb], &bf[np][0]);
                        mma16816h(acc[mb][np * 2 + 1], af[mb], &bf[np][2]);
                    } else {
                        mma16816(acc[mb][np * 2],     af[mb], &bf[np][0]);
                        mma16816(acc[mb][np * 2 + 1], af[mb], &bf[np][2]);
                    }
                }
        }
        __syncthreads();
        if (c + 2 < NCH) {
            int cn = c + 2, pass = cn >> 4, k0 = (cn & 15) * 64;
            gemm_issue(t, sbase + (cn & 1) * GSTAGE,
                       pA[pass] + (size_t)m0 * (DM * 2) + k0 * 2, pB[pass] + k0 * 2);
        }
    }

    const int rr = lane >> 2, c2 = (lane & 3) * 2;
#pragma unroll
    for (int mb = 0; mb < 4; mb++) {
        int row0 = m0 + wm * 64 + mb * 16 + rr;
#pragma unroll
        for (int nb = 0; nb < 8; nb++) {
            int col = ccol + wn * 64 + nb * 8 + c2;
            *(float2*)&C[(size_t)row0 * DM + col]       = make_float2(acc[mb][nb][0], acc[mb][nb][1]);
            *(float2*)&C[(size_t)(row0 + 8) * DM + col] = make_float2(acc[mb][nb][2], acc[mb][nb][3]);
        }
    }
}

// ---------------- RoPE + fp16 convert (Q scaled 1/8; K, V hi only) ---------
__global__ void rope_cvt_kernel() {
    __shared__ float cs[32], sn[32];
    const int s = blockIdx.x, t = threadIdx.x;
    if (t < 32) {
        double invf = pow(10000.0, -((double)(2 * t)) / 64.0);
        double si, co;
        sincos((double)s * invf, &si, &co);
        cs[t] = (float)co; sn[t] = (float)si;
    }
    __syncthreads();
    for (int p = t; p < 512; p += 256) {
        int hh = p >> 5, i = p & 31;
        int base = s * DM + hh * 64 + i;
        float c = cs[i], si = sn[i];
        float q1 = g_Q[base], q2 = g_Q[base + 32];
        g_qh[base]      = __float2half_rn((q1 * c - q2 * si) * 0.125f);
        g_qh[base + 32] = __float2half_rn((q2 * c + q1 * si) * 0.125f);
        float k1 = g_K[base], k2 = g_K[base + 32];
        g_kh[base]      = __float2half_rn(k1 * c - k2 * si);
        g_kh[base + 32] = __float2half_rn(k2 * c + k1 * si);
    }
    for (int i = t; i < DM; i += 256) {
        g_vh[s * DM + i] = __float2half_rn(g_V[s * DM + i]);
    }
}

// ---------------- Flash attention: fp16 HMMA, S 1-pass, PV 1-pass -----------
// CTA = (q-tile 128 rows, head). 256 thr / 8 warps; warp = 16 q-rows x full 64 kv.
#define F_STG 18432            // stage s at F_STG + s*F_STGSZ: Kh, Vh (9216 each)
#define F_T   9216
#define F_STGSZ 18432
#define FLASH_SMEM (18432 + 2 * F_STGSZ)   // 55296

__device__ __forceinline__ void flash_issue_kv(int t, uint32_t stg, int kbase, int h) {
    const size_t rowoff = (size_t)kbase * DM + h * 64;
    const __half* srcs[2] = {g_kh + rowoff, g_vh + rowoff};
#pragma unroll
    for (int i = 0; i < 4; i++) {
        int idx = t + i * 256;              // 0..1023
        int mat = idx >> 9;                 // 0..1
        int rem = idx & 511;
        int row = rem >> 3, ch = rem & 7;
        cp_async16(stg + mat * F_T + row * SKB + ch * 16,
                   (const char*)srcs[mat] + (size_t)row * (DM * 2) + ch * 16);
    }
    CP_COMMIT();
}

__global__ __launch_bounds__(256)
void flash_kernel() {
    extern __shared__ char dsm[];
    const uint32_t sbase = smem_u32(dsm);
    const int t = threadIdx.x, lane = t & 31, wid = t >> 5;
    const int h = blockIdx.y;
    const int qt = (int)gridDim.x - 1 - (int)blockIdx.x;   // heavy first
    const int qbase = qt * 128;
    const int ntiles = 2 * qt + 2;

    // Q load + kv tile0 (one group), then kv tile1
    {
        const size_t rowoff = (size_t)qbase * DM + h * 64;
#pragma unroll
        for (int i = 0; i < 4; i++) {
            int idx = t + i * 256;           // 0..1023
            int row = idx >> 3, ch = idx & 7;
            cp_async16(sbase + row * SKB + ch * 16,
                       (const char*)(g_qh + rowoff) + (size_t)row * (DM * 2) + ch * 16);
        }
        flash_issue_kv(t, sbase + F_STG, 0, h);            // commits Q + tile0
        flash_issue_kv(t, sbase + F_STG + F_STGSZ, 64, h); // tile 1
    }

    CP_WAIT1();          // Q + tile0 ready
    __syncthreads();

    // preload Q fragments (persistent)
    const int q = lane >> 3, r = lane & 7;
    uint32_t qf[4][4];
#pragma unroll
    for (int ks = 0; ks < 4; ks++) {
        uint32_t ro = (wid * 16 + (q & 1) * 8 + r) * SKB + (ks * 16 + (q >> 1) * 8) * 2;
        ldsm_x4(qf[ks], sbase + ro);
    }

    float o[8][4];
#pragma unroll
    for (int a = 0; a < 8; a++)
#pragma unroll
        for (int b = 0; b < 4; b++) o[a][b] = 0.f;
    float m0r = -1e30f, m1r = -1e30f, l0 = 0.f, l1 = 0.f;

    const int rr = lane >> 2, c2 = (lane & 3) * 2;
    const int qlo = qbase + wid * 16;
    const int qr0 = qlo + rr, qr1 = qr0 + 8;

    for (int kt = 0; kt < ntiles; kt++) {
        const uint32_t stg = sbase + F_STG + (kt & 1) * F_STGSZ;

        if (kt * 64 <= qlo + 15) {     // warp tile not fully masked
            float s[8][4];
#pragma unroll
            for (int a = 0; a < 8; a++)
#pragma unroll
                for (int b = 0; b < 4; b++) s[a][b] = 0.f;

            // S = Q * Kh  (1-pass)
#pragma unroll
            for (int ks = 0; ks < 4; ks++) {
#pragma unroll
                for (int np = 0; np < 4; np++) {
                    uint32_t kf[4];
                    uint32_t ro = (np * 16 + (q >> 1) * 8 + r) * SKB + (ks * 16 + (q & 1) * 8) * 2;
                    ldsm_x4(kf, stg + 0 * F_T + ro);           // Kh
                    mma16816h(s[np * 2],     qf[ks], &kf[0]);
                    mma16816h(s[np * 2 + 1], qf[ks], &kf[2]);
                }
            }

            // causal mask (diagonal-straddling tiles only)
            if (kt * 64 + 63 > qlo) {
#pragma unroll
                for (int nb = 0; nb < 8; nb++) {
                    int kc = kt * 64 + nb * 8 + c2;
                    if (kc     > qr0) s[nb][0] = -1e30f;
                    if (kc + 1 > qr0) s[nb][1] = -1e30f;
                    if (kc     > qr1) s[nb][2] = -1e30f;
                    if (kc + 1 > qr1) s[nb][3] = -1e30f;
                }
            }

            // online softmax
            float mx0 = -1e30f, mx1 = -1e30f;
#pragma unroll
            for (int nb = 0; nb < 8; nb++) {
                mx0 = fmaxf(mx0, fmaxf(s[nb][0], s[nb][1]));
                mx1 = fmaxf(mx1, fmaxf(s[nb][2], s[nb][3]));
            }
            mx0 = fmaxf(mx0, __shfl_xor_sync(0xffffffffu, mx0, 1));
            mx0 = fmaxf(mx0, __shfl_xor_sync(0xffffffffu, mx0, 2));
            mx1 = fmaxf(mx1, __shfl_xor_sync(0xffffffffu, mx1, 1));
            mx1 = fmaxf(mx1, __shfl_xor_sync(0xffffffffu, mx1, 2));
            float mn0 = fmaxf(m0r, mx0), mn1 = fmaxf(m1r, mx1);
            float al0 = __expf(m0r - mn0), al1 = __expf(m1r - mn1);
            float sum0 = 0.f, sum1 = 0.f;
#pragma unroll
            for (int nb = 0; nb < 8; nb++) {
                s[nb][0] = __expf(s[nb][0] - mn0); sum0 += s[nb][0];
                s[nb][1] = __expf(s[nb][1] - mn0); sum0 += s[nb][1];
                s[nb][2] = __expf(s[nb][2] - mn1); sum1 += s[nb][2];
                s[nb][3] = __expf(s[nb][3] - mn1); sum1 += s[nb][3];
            }
            sum0 += __shfl_xor_sync(0xffffffffu, sum0, 1);
            sum0 += __shfl_xor_sync(0xffffffffu, sum0, 2);
            sum1 += __shfl_xor_sync(0xffffffffu, sum1, 1);
            sum1 += __shfl_xor_sync(0xffffffffu, sum1, 2);
            l0 = l0 * al0 + sum0;  l1 = l1 * al1 + sum1;
            m0r = mn0;  m1r = mn1;
#pragma unroll
            for (int nb = 0; nb < 8; nb++) {
                o[nb][0] *= al0; o[nb][1] *= al0;
                o[nb][2] *= al1; o[nb][3] *= al1;
            }

            // PV: O += P * Vh (1-pass, P rounded to fp16)
#pragma unroll
            for (int ks = 0; ks < 4; ks++) {
                uint32_t ph[4];
#pragma unroll
                for (int half = 0; half < 2; half++) {
                    int nb = 2 * ks + half;
                    ph[half * 2]     = pack2h(s[nb][0], s[nb][1]);
                    ph[half * 2 + 1] = pack2h(s[nb][2], s[nb][3]);
                }
#pragma unroll
                for (int dp = 0; dp < 4; dp++) {
                    uint32_t vf[4];
                    uint32_t ro = (ks * 16 + (q & 1) * 8 + r) * SKB + (dp * 16 + (q >> 1) * 8) * 2;
                    ldsm_x4t(vf, stg + 1 * F_T + ro);          // Vh
                    mma16816h(o[dp * 2],     ph, &vf[0]);
                    mma16816h(o[dp * 2 + 1], ph, &vf[2]);
                }
            }
        }

        __syncthreads();          // done reading this stage
        if (kt + 2 < ntiles)
            flash_issue_kv(t, sbase + F_STG + (kt & 1) * F_STGSZ, (kt + 2) * 64, h);
        if (kt + 1 < ntiles) {
            if (kt + 2 < ntiles) { CP_WAIT1(); } else { CP_WAIT0(); }
            __syncthreads();      // tile kt+1 data visible to all
        }
    }

    // epilogue: normalize, split hi/lo, store bf16x2 (exact input to 3-pass proj)
    float inv0 = 1.f / l0, inv1 = 1.f / l1;
#pragma unroll
    for (int nb = 0; nb < 8; nb++) {
        int col = h * 64 + nb * 8 + c2;
        __nv_bfloat16 h0, e0, h1, e1;
        split1(o[nb][0] * inv0, h0, e0);
        split1(o[nb][1] * inv0, h1, e1);
        *(uint32_t*)&g_ah[(size_t)qr0 * DM + col] = pack2(h0, h1);
        *(uint32_t*)&g_al[(size_t)qr0 * DM + col] = pack2(e0, e1);
        split1(o[nb][2] * inv1, h0, e0);
        split1(o[nb][3] * inv1, h1, e1);
        *(uint32_t*)&g_ah[(size_t)qr1 * DM + col] = pack2(h0, h1);
        *(uint32_t*)&g_al[(size_t)qr1 * DM + col] = pack2(e0, e1);
    }
}

// ---------------- launch ----------------
extern "C" void kernel_launch(void* const* d_in, const int* in_sizes, int n_in,
                              void* d_out, int out_size) {
    const float* x  = (const float*)d_in[0];
    const float* Wq = (const float*)d_in[1];
    const float* Wk = (const float*)d_in[2];
    const float* Wv = (const float*)d_in[3];
    const float* Wo = (const float*)d_in[4];
    float* out = (float*)d_out;

    cudaFuncSetAttribute(mma_gemm_kernel<0>, cudaFuncAttributeMaxDynamicSharedMemorySize, GEMM_SMEM);
    cudaFuncSetAttribute(mma_gemm_kernel<1>, cudaFuncAttributeMaxDynamicSharedMemorySize, GEMM_SMEM);
    cudaFuncSetAttribute(flash_kernel,       cudaFuncAttributeMaxDynamicSharedMemorySize, FLASH_SMEM);

    cvt_all_kernel<<<8192, 256>>>(x, Wq, Wk, Wv, Wo);

    mma_gemm_kernel<0><<<dim3(3 * DM / 128, SEQ / 128), 128, GEMM_SMEM>>>(nullptr);

    rope_cvt_kernel<<<SEQ, 256>>>();

    flash_kernel<<<dim3(SEQ / 128, NH), 256, FLASH_SMEM>>>();

    mma_gemm_kernel<1><<<dim3(DM / 128, SEQ / 128), 128, GEMM_SMEM>>>(out);
}

// round 8
// speedup vs baseline: 1.7994x; 1.0871x over previous
#include <cuda_runtime.h>
#include <cuda_bf16.h>
#include <cuda_fp16.h>
#include <math.h>
#include <stdint.h>

// Problem constants
#define SEQ   4096
#define DM    1024
#define NH    16
#define DH    64

// ---------------- scratch (no allocations allowed) ----------------
__device__ float g_Q[SEQ * DM];
__device__ float g_K[SEQ * DM];
__device__ float g_V[SEQ * DM];

// QKV GEMM operands (fp16): x hi/lo, W hi only (Wq,Wk,Wv stacked rows)
__device__ __half g_x16h[SEQ * DM], g_x16l[SEQ * DM];
__device__ __half g_w16[3 * DM * DM];
// proj GEMM operands (fp16 2-pass)
__device__ __half g_w16o[DM * DM];
__device__ __half g_a16h[SEQ * DM], g_a16l[SEQ * DM];   // attention out split

// flash operands (fp16)
__device__ __half g_qh[SEQ * DM];   // roped Q, pre-scaled by (1/8)*log2e
__device__ __half g_kh[SEQ * DM];   // roped K
__device__ __half g_vh[SEQ * DM];   // V

// ---------------- low-level helpers ----------------
__device__ __forceinline__ uint32_t smem_u32(const void* p) {
    uint32_t a;
    asm("{ .reg .u64 t; cvta.to.shared.u64 t, %1; cvt.u32.u64 %0, t; }" : "=r"(a) : "l"(p));
    return a;
}
__device__ __forceinline__ void cp_async16(uint32_t sa, const void* ga) {
    asm volatile("cp.async.cg.shared.global [%0], [%1], 16;" :: "r"(sa), "l"(ga));
}
#define CP_COMMIT() asm volatile("cp.async.commit_group;" ::: "memory")
#define CP_WAIT1()  asm volatile("cp.async.wait_group 1;" ::: "memory")
#define CP_WAIT0()  asm volatile("cp.async.wait_group 0;" ::: "memory")

__device__ __forceinline__ void ldsm_x4(uint32_t* r, uint32_t addr) {
    asm volatile("ldmatrix.sync.aligned.m8n8.x4.shared.b16 {%0,%1,%2,%3}, [%4];"
        : "=r"(r[0]), "=r"(r[1]), "=r"(r[2]), "=r"(r[3]) : "r"(addr));
}
__device__ __forceinline__ void ldsm_x4t(uint32_t* r, uint32_t addr) {
    asm volatile("ldmatrix.sync.aligned.m8n8.x4.trans.shared.b16 {%0,%1,%2,%3}, [%4];"
        : "=r"(r[0]), "=r"(r[1]), "=r"(r[2]), "=r"(r[3]) : "r"(addr));
}
__device__ __forceinline__ void ldsm_x2t(uint32_t* r, uint32_t addr) {
    asm volatile("ldmatrix.sync.aligned.m8n8.x2.trans.shared.b16 {%0,%1}, [%2];"
        : "=r"(r[0]), "=r"(r[1]) : "r"(addr));
}
// fp16 mma
__device__ __forceinline__ void mma16816h(float* d, const uint32_t* a, const uint32_t* b) {
    asm volatile("mma.sync.aligned.m16n8k16.row.col.f32.f16.f16.f32 "
        "{%0,%1,%2,%3}, {%4,%5,%6,%7}, {%8,%9}, {%0,%1,%2,%3};"
        : "+f"(d[0]), "+f"(d[1]), "+f"(d[2]), "+f"(d[3])
        : "r"(a[0]), "r"(a[1]), "r"(a[2]), "r"(a[3]), "r"(b[0]), "r"(b[1]));
}
__device__ __forceinline__ void split1h(float v, __half& h, __half& l) {
    h = __float2half_rn(v);
    l = __float2half_rn(v - __half2float(h));
}
__device__ __forceinline__ uint32_t packh2(__half2 v) {
    uint32_t u; memcpy(&u, &v, 4); return u;
}

// ---------------- fused convert kernel (all 5 inputs, one launch) ----------
// b in [0,4096): x -> fp16 hi/lo
// b in [4096,7168): Wq/Wk/Wv -> fp16 hi (stacked)
// b in [7168,8192): Wo -> fp16 hi
__global__ void cvt_all_kernel(const float* __restrict__ x,
                               const float* __restrict__ Wq,
                               const float* __restrict__ Wk,
                               const float* __restrict__ Wv,
                               const float* __restrict__ Wo) {
    int b = blockIdx.x;
    if (b < 4096) {
        int i = (b * 256 + threadIdx.x) * 4;
        float4 v = *(const float4*)&x[i];
        __half h0, l0, h1, l1, h2, l2, h3, l3;
        split1h(v.x, h0, l0); split1h(v.y, h1, l1);
        split1h(v.z, h2, l2); split1h(v.w, h3, l3);
        __half2 a;
        a.x = h0; a.y = h1; *(uint32_t*)&g_x16h[i]     = packh2(a);
        a.x = h2; a.y = h3; *(uint32_t*)&g_x16h[i + 2] = packh2(a);
        a.x = l0; a.y = l1; *(uint32_t*)&g_x16l[i]     = packh2(a);
        a.x = l2; a.y = l3; *(uint32_t*)&g_x16l[i + 2] = packh2(a);
    } else {
        const float* src; __half* dst; int si, di;
        if (b < 7168) {
            int bb = b - 4096;                 // 0..3071
            int mat = bb >> 10;                // 0..2
            src = (mat == 0) ? Wq : (mat == 1 ? Wk : Wv);
            si = ((bb & 1023) * 256 + threadIdx.x) * 4;
            di = (bb * 256 + threadIdx.x) * 4;
            dst = g_w16;
        } else {
            si = ((b - 7168) * 256 + threadIdx.x) * 4;
            di = si; src = Wo; dst = g_w16o;
        }
        float4 v = *(const float4*)&src[si];
        __half2 a;
        a.x = __float2half_rn(v.x); a.y = __float2half_rn(v.y);
        *(uint32_t*)&dst[di] = packh2(a);
        a.x = __float2half_rn(v.z); a.y = __float2half_rn(v.w);
        *(uint32_t*)&dst[di + 2] = packh2(a);
    }
}

// ---------------- HMMA fp16 2-pass NT GEMM ----------------
// C[m,n] = sum_k A[m,k]*B[n,k]; BM=BN=128, BK=64, 128 threads, 4 warps of 64x64.
#define SKB 144                    // smem row stride bytes (72 elems, conflict-free ldsm)
#define GTILE (128 * SKB)          // 18432 B per matrix tile
#define GSTAGE (2 * GTILE)         // A+B
#define GEMM_SMEM (2 * GSTAGE)     // double buffer: 73728

__device__ __forceinline__ void gemm_issue(int t, uint32_t st,
                                           const char* A, const char* B) {
#pragma unroll
    for (int i = 0; i < 8; i++) {
        int idx = t + i * 128;
        int row = idx >> 3, ch = idx & 7;
        cp_async16(st + row * SKB + ch * 16, A + (size_t)row * (DM * 2) + ch * 16);
        cp_async16(st + GTILE + row * SKB + ch * 16, B + (size_t)row * (DM * 2) + ch * 16);
    }
    CP_COMMIT();
}

template<int WHICH>
__global__ __launch_bounds__(128)
void mma_gemm_kernel(float* __restrict__ outp) {
    constexpr int NCH = 32;        // 2 passes x 16 chunks
    extern __shared__ char dsm[];
    const uint32_t sbase = smem_u32(dsm);
    const int t = threadIdx.x, lane = t & 31, wid = t >> 5;
    const int nt = blockIdx.x, mt = blockIdx.y;
    const int m0 = mt * 128, n0 = nt * 128;

    const char *pA[2], *pB[2];
    float* C; int ccol;
    if (WHICH == 0) {
        pA[0] = (const char*)g_x16h; pA[1] = (const char*)g_x16l;
        const char* bh = (const char*)(g_w16 + (size_t)n0 * DM);
        pB[0] = bh; pB[1] = bh;
        int mat = nt >> 3;
        C = (mat == 0) ? g_Q : (mat == 1 ? g_K : g_V);
        ccol = (nt & 7) * 128;
    } else {
        pA[0] = (const char*)g_a16h; pA[1] = (const char*)g_a16l;
        const char* bh = (const char*)(g_w16o + (size_t)n0 * DM);
        pB[0] = bh; pB[1] = bh;
        C = outp; ccol = n0;
    }

    float acc[4][8][4];
#pragma unroll
    for (int a = 0; a < 4; a++)
#pragma unroll
        for (int b = 0; b < 8; b++)
#pragma unroll
            for (int c = 0; c < 4; c++) acc[a][b][c] = 0.f;

#pragma unroll
    for (int c = 0; c < 2; c++) {
        int pass = c >> 4, k0 = (c & 15) * 64;
        gemm_issue(t, sbase + (c & 1) * GSTAGE,
                   pA[pass] + (size_t)m0 * (DM * 2) + k0 * 2, pB[pass] + k0 * 2);
    }

    const int wm = wid & 1, wn = wid >> 1;      // 2x2 warps, 64x64 each
    const int q = lane >> 3, r = lane & 7;

    for (int c = 0; c < NCH; c++) {
        if (c + 1 < NCH) { CP_WAIT1(); } else { CP_WAIT0(); }
        __syncthreads();

        const uint32_t sa = sbase + (c & 1) * GSTAGE + (wm * 64) * SKB;
        const uint32_t sb = sbase + (c & 1) * GSTAGE + GTILE + (wn * 64) * SKB;
#pragma unroll
        for (int ks = 0; ks < 4; ks++) {
            uint32_t af[4][4], bf[4][4];
#pragma unroll
            for (int mb = 0; mb < 4; mb++)
                ldsm_x4(af[mb], sa + (mb * 16 + (q & 1) * 8 + r) * SKB
                                   + (ks * 16 + (q >> 1) * 8) * 2);
#pragma unroll
            for (int np = 0; np < 4; np++)
                ldsm_x4(bf[np], sb + (np * 16 + (q >> 1) * 8 + r) * SKB
                                   + (ks * 16 + (q & 1) * 8) * 2);
#pragma unroll
            for (int mb = 0; mb < 4; mb++)
#pragma unroll
                for (int np = 0; np < 4; np++) {
                    mma16816h(acc[mb][np * 2],     af[mb], &bf[np][0]);
                    mma16816h(acc[mb][np * 2 + 1], af[mb], &bf[np][2]);
                }
        }
        __syncthreads();
        if (c + 2 < NCH) {
            int cn = c + 2, pass = cn >> 4, k0 = (cn & 15) * 64;
            gemm_issue(t, sbase + (cn & 1) * GSTAGE,
                       pA[pass] + (size_t)m0 * (DM * 2) + k0 * 2, pB[pass] + k0 * 2);
        }
    }

    const int rr = lane >> 2, c2 = (lane & 3) * 2;
#pragma unroll
    for (int mb = 0; mb < 4; mb++) {
        int row0 = m0 + wm * 64 + mb * 16 + rr;
#pragma unroll
        for (int nb = 0; nb < 8; nb++) {
            int col = ccol + wn * 64 + nb * 8 + c2;
            *(float2*)&C[(size_t)row0 * DM + col]       = make_float2(acc[mb][nb][0], acc[mb][nb][1]);
            *(float2*)&C[(size_t)(row0 + 8) * DM + col] = make_float2(acc[mb][nb][2], acc[mb][nb][3]);
        }
    }
}

// -------- RoPE + fp16 convert (Q scaled by (1/8)*log2e; K, V plain) --------
#define QSCALE 0.18033688011112042f   // 0.125 * log2(e)
__global__ void rope_cvt_kernel() {
    __shared__ float cs[32], sn[32];
    const int s = blockIdx.x, t = threadIdx.x;
    if (t < 32) {
        double invf = pow(10000.0, -((double)(2 * t)) / 64.0);
        double si, co;
        sincos((double)s * invf, &si, &co);
        cs[t] = (float)co; sn[t] = (float)si;
    }
    __syncthreads();
    for (int p = t; p < 512; p += 256) {
        int hh = p >> 5, i = p & 31;
        int base = s * DM + hh * 64 + i;
        float c = cs[i], si = sn[i];
        float q1 = g_Q[base], q2 = g_Q[base + 32];
        g_qh[base]      = __float2half_rn((q1 * c - q2 * si) * QSCALE);
        g_qh[base + 32] = __float2half_rn((q2 * c + q1 * si) * QSCALE);
        float k1 = g_K[base], k2 = g_K[base + 32];
        g_kh[base]      = __float2half_rn(k1 * c - k2 * si);
        g_kh[base + 32] = __float2half_rn(k2 * c + k1 * si);
    }
    for (int i = t; i < DM; i += 256) {
        g_vh[s * DM + i] = __float2half_rn(g_V[s * DM + i]);
    }
}

// ---------------- Flash attention: fp16 HMMA, exp2-domain softmax -----------
// CTA = (q-tile 128 rows, head). 256 thr / 8 warps; warp = 16 q-rows x full 64 kv.
// V tile rows are 72 halves wide; cols 64..71 hold {1,0,...,0} -> row-sum via MMA.
#define F_STG 18432            // stage s at F_STG + s*F_STGSZ: Kh, Vh (9216 each)
#define F_T   9216
#define F_STGSZ 18432
#define FLASH_SMEM (18432 + 2 * F_STGSZ)   // 55296

__device__ __forceinline__ void flash_issue_kv(int t, uint32_t stg, int kbase, int h) {
    const size_t rowoff = (size_t)kbase * DM + h * 64;
    const __half* srcs[2] = {g_kh + rowoff, g_vh + rowoff};
#pragma unroll
    for (int i = 0; i < 4; i++) {
        int idx = t + i * 256;              // 0..1023
        int mat = idx >> 9;                 // 0..1
        int rem = idx & 511;
        int row = rem >> 3, ch = rem & 7;
        cp_async16(stg + mat * F_T + row * SKB + ch * 16,
                   (const char*)srcs[mat] + (size_t)row * (DM * 2) + ch * 16);
    }
    CP_COMMIT();
}

__global__ __launch_bounds__(256)
void flash_kernel() {
    extern __shared__ char dsm[];
    const uint32_t sbase = smem_u32(dsm);
    const int t = threadIdx.x, lane = t & 31, wid = t >> 5;
    const int h = blockIdx.y;
    const int qt = (int)gridDim.x - 1 - (int)blockIdx.x;   // heavy first
    const int qbase = qt * 128;
    const int ntiles = 2 * qt + 2;

    // Q load + kv tile0 (one group), then kv tile1
    {
        const size_t rowoff = (size_t)qbase * DM + h * 64;
#pragma unroll
        for (int i = 0; i < 4; i++) {
            int idx = t + i * 256;           // 0..1023
            int row = idx >> 3, ch = idx & 7;
            cp_async16(sbase + row * SKB + ch * 16,
                       (const char*)(g_qh + rowoff) + (size_t)row * (DM * 2) + ch * 16);
        }
        flash_issue_kv(t, sbase + F_STG, 0, h);            // commits Q + tile0
        flash_issue_kv(t, sbase + F_STG + F_STGSZ, 64, h); // tile 1
    }

    // Ones-column pad for both V stage buffers (bytes 128..143 of each V row;
    // cp.async only writes bytes 0..127, so this persists across stage reuse).
    if (t < 128) {
        int buf = t >> 6, row = t & 63;
        uint32_t addr = sbase + F_STG + buf * F_STGSZ + F_T + row * SKB + 128;
        uint4 ones = make_uint4(0x00003C00u, 0u, 0u, 0u);  // half {1,0,0,0,0,0,0,0}
        *(uint4*)(dsm + (addr - sbase)) = ones;
    }

    CP_WAIT1();          // Q + tile0 ready
    __syncthreads();

    // preload Q fragments (persistent)
    const int q = lane >> 3, r = lane & 7;
    uint32_t qf[4][4];
#pragma unroll
    for (int ks = 0; ks < 4; ks++) {
        uint32_t ro = (wid * 16 + (q & 1) * 8 + r) * SKB + (ks * 16 + (q >> 1) * 8) * 2;
        ldsm_x4(qf[ks], sbase + ro);
    }

    float o[8][4], o_sum[4];
#pragma unroll
    for (int a = 0; a < 8; a++)
#pragma unroll
        for (int b = 0; b < 4; b++) o[a][b] = 0.f;
#pragma unroll
    for (int b = 0; b < 4; b++) o_sum[b] = 0.f;
    float m0r = -1e30f, m1r = -1e30f;

    const int rr = lane >> 2, c2 = (lane & 3) * 2;
    const int qlo = qbase + wid * 16;
    const int qr0 = qlo + rr, qr1 = qr0 + 8;
    const int l16 = lane & 15;

    for (int kt = 0; kt < ntiles; kt++) {
        const uint32_t stg = sbase + F_STG + (kt & 1) * F_STGSZ;

        if (kt * 64 <= qlo + 15) {     // warp tile not fully masked
            float s[8][4];
#pragma unroll
            for (int a = 0; a < 8; a++)
#pragma unroll
                for (int b = 0; b < 4; b++) s[a][b] = 0.f;

            // S = Q * K (logits in log2 domain; Q pre-scaled by log2e/8)
#pragma unroll
            for (int ks = 0; ks < 4; ks++) {
#pragma unroll
                for (int np = 0; np < 4; np++) {
                    uint32_t kf[4];
                    uint32_t ro = (np * 16 + (q >> 1) * 8 + r) * SKB + (ks * 16 + (q & 1) * 8) * 2;
                    ldsm_x4(kf, stg + 0 * F_T + ro);
                    mma16816h(s[np * 2],     qf[ks], &kf[0]);
                    mma16816h(s[np * 2 + 1], qf[ks], &kf[2]);
                }
            }

            // causal mask (diagonal-straddling tiles only)
            if (kt * 64 + 63 > qlo) {
#pragma unroll
                for (int nb = 0; nb < 8; nb++) {
                    int kc = kt * 64 + nb * 8 + c2;
                    if (kc     > qr0) s[nb][0] = -1e30f;
                    if (kc + 1 > qr0) s[nb][1] = -1e30f;
                    if (kc     > qr1) s[nb][2] = -1e30f;
                    if (kc + 1 > qr1) s[nb][3] = -1e30f;
                }
            }

            // online max (log2 domain)
            float mx0 = -1e30f, mx1 = -1e30f;
#pragma unroll
            for (int nb = 0; nb < 8; nb++) {
                mx0 = fmaxf(mx0, fmaxf(s[nb][0], s[nb][1]));
                mx1 = fmaxf(mx1, fmaxf(s[nb][2], s[nb][3]));
            }
            mx0 = fmaxf(mx0, __shfl_xor_sync(0xffffffffu, mx0, 1));
            mx0 = fmaxf(mx0, __shfl_xor_sync(0xffffffffu, mx0, 2));
            mx1 = fmaxf(mx1, __shfl_xor_sync(0xffffffffu, mx1, 1));
            mx1 = fmaxf(mx1, __shfl_xor_sync(0xffffffffu, mx1, 2));
            float mn0 = fmaxf(m0r, mx0), mn1 = fmaxf(m1r, mx1);
            float al0 = exp2f(m0r - mn0), al1 = exp2f(m1r - mn1);
            m0r = mn0;  m1r = mn1;
#pragma unroll
            for (int nb = 0; nb < 8; nb++) {
                o[nb][0] *= al0; o[nb][1] *= al0;
                o[nb][2] *= al1; o[nb][3] *= al1;
            }
            o_sum[0] *= al0; o_sum[1] *= al0;
            o_sum[2] *= al1; o_sum[3] *= al1;

            // P = exp2(s - m) computed in fp16x2; PV (+ ones-column row sum)
#pragma unroll
            for (int ks = 0; ks < 4; ks++) {
                uint32_t ph[4];
#pragma unroll
                for (int hf = 0; hf < 2; hf++) {
                    int nb = 2 * ks + hf;
                    __half2 e0 = h2exp2(__floats2half2_rn(s[nb][0] - mn0, s[nb][1] - mn0));
                    __half2 e1 = h2exp2(__floats2half2_rn(s[nb][2] - mn1, s[nb][3] - mn1));
                    ph[hf * 2]     = packh2(e0);
                    ph[hf * 2 + 1] = packh2(e1);
                }
#pragma unroll
                for (int dp = 0; dp < 4; dp++) {
                    uint32_t vf[4];
                    uint32_t ro = (ks * 16 + (q & 1) * 8 + r) * SKB + (dp * 16 + (q >> 1) * 8) * 2;
                    ldsm_x4t(vf, stg + 1 * F_T + ro);
                    mma16816h(o[dp * 2],     ph, &vf[0]);
                    mma16816h(o[dp * 2 + 1], ph, &vf[2]);
                }
                uint32_t bs[2];
                ldsm_x2t(bs, stg + 1 * F_T + (ks * 16 + l16) * SKB + 128);
                mma16816h(o_sum, ph, bs);
            }
        }

        __syncthreads();          // done reading this stage
        if (kt + 2 < ntiles)
            flash_issue_kv(t, sbase + F_STG + (kt & 1) * F_STGSZ, (kt + 2) * 64, h);
        if (kt + 1 < ntiles) {
            if (kt + 2 < ntiles) { CP_WAIT1(); } else { CP_WAIT0(); }
            __syncthreads();      // tile kt+1 data visible to all
        }
    }

    // epilogue: l lives in o_sum col 0 (lanes with lane&3==0); broadcast in quad
    float l0 = __shfl_sync(0xffffffffu, o_sum[0], lane & 0x1C);
    float l1 = __shfl_sync(0xffffffffu, o_sum[2], lane & 0x1C);
    float inv0 = 1.f / l0, inv1 = 1.f / l1;
#pragma unroll
    for (int nb = 0; nb < 8; nb++) {
        int col = h * 64 + nb * 8 + c2;
        __half h0, e0, h1, e1;  __half2 a;
        split1h(o[nb][0] * inv0, h0, e0);
        split1h(o[nb][1] * inv0, h1, e1);
        a.x = h0; a.y = h1; *(uint32_t*)&g_a16h[(size_t)qr0 * DM + col] = packh2(a);
        a.x = e0; a.y = e1; *(uint32_t*)&g_a16l[(size_t)qr0 * DM + col] = packh2(a);
        split1h(o[nb][2] * inv1, h0, e0);
        split1h(o[nb][3] * inv1, h1, e1);
        a.x = h0; a.y = h1; *(uint32_t*)&g_a16h[(size_t)qr1 * DM + col] = packh2(a);
        a.x = e0; a.y = e1; *(uint32_t*)&g_a16l[(size_t)qr1 * DM + col] = packh2(a);
    }
}

// ---------------- launch ----------------
extern "C" void kernel_launch(void* const* d_in, const int* in_sizes, int n_in,
                              void* d_out, int out_size) {
    const float* x  = (const float*)d_in[0];
    const float* Wq = (const float*)d_in[1];
    const float* Wk = (const float*)d_in[2];
    const float* Wv = (const float*)d_in[3];
    const float* Wo = (const float*)d_in[4];
    float* out = (float*)d_out;

    cudaFuncSetAttribute(mma_gemm_kernel<0>, cudaFuncAttributeMaxDynamicSharedMemorySize, GEMM_SMEM);
    cudaFuncSetAttribute(mma_gemm_kernel<1>, cudaFuncAttributeMaxDynamicSharedMemorySize, GEMM_SMEM);
    cudaFuncSetAttribute(flash_kernel,       cudaFuncAttributeMaxDynamicSharedMemorySize, FLASH_SMEM);

    cvt_all_kernel<<<8192, 256>>>(x, Wq, Wk, Wv, Wo);

    mma_gemm_kernel<0><<<dim3(3 * DM / 128, SEQ / 128), 128, GEMM_SMEM>>>(nullptr);

    rope_cvt_kernel<<<SEQ, 256>>>();

    flash_kernel<<<dim3(SEQ / 128, NH), 256, FLASH_SMEM>>>();

    mma_gemm_kernel<1><<<dim3(DM / 128, SEQ / 128), 128, GEMM_SMEM>>>(out);
}

// round 9
// speedup vs baseline: 1.9405x; 1.0785x over previous
#include <cuda_runtime.h>
#include <cuda_fp16.h>
#include <math.h>
#include <stdint.h>

// Problem constants
#define SEQ   4096
#define DM    1024
#define NH    16
#define DH    64

// ---------------- scratch (no allocations allowed) ----------------
// QKV GEMM operands (fp16): x hi/lo, W hi only (Wq,Wk,Wv stacked rows)
__device__ __half g_x16h[SEQ * DM], g_x16l[SEQ * DM];
__device__ __half g_w16[3 * DM * DM];
// proj GEMM operands (fp16, 1-pass)
__device__ __half g_w16o[DM * DM];
__device__ __half g_a16h[SEQ * DM];        // attention out (fp16)

// flash operands (fp16), written directly by the QKV epilogue
__device__ __half g_qh[SEQ * DM];   // roped Q, pre-scaled by (1/8)*log2e
__device__ __half g_kh[SEQ * DM];   // roped K
__device__ __half g_vh[SEQ * DM];   // V

// rope table: [s][i*2]=cos, [i*2+1]=sin  (i = 0..31)
__device__ float g_rope[SEQ][64];

// ---------------- low-level helpers ----------------
__device__ __forceinline__ uint32_t smem_u32(const void* p) {
    uint32_t a;
    asm("{ .reg .u64 t; cvta.to.shared.u64 t, %1; cvt.u32.u64 %0, t; }" : "=r"(a) : "l"(p));
    return a;
}
__device__ __forceinline__ void cp_async16(uint32_t sa, const void* ga) {
    asm volatile("cp.async.cg.shared.global [%0], [%1], 16;" :: "r"(sa), "l"(ga));
}
#define CP_COMMIT() asm volatile("cp.async.commit_group;" ::: "memory")
#define CP_WAIT1()  asm volatile("cp.async.wait_group 1;" ::: "memory")
#define CP_WAIT0()  asm volatile("cp.async.wait_group 0;" ::: "memory")

__device__ __forceinline__ void ldsm_x4(uint32_t* r, uint32_t addr) {
    asm volatile("ldmatrix.sync.aligned.m8n8.x4.shared.b16 {%0,%1,%2,%3}, [%4];"
        : "=r"(r[0]), "=r"(r[1]), "=r"(r[2]), "=r"(r[3]) : "r"(addr));
}
__device__ __forceinline__ void ldsm_x4t(uint32_t* r, uint32_t addr) {
    asm volatile("ldmatrix.sync.aligned.m8n8.x4.trans.shared.b16 {%0,%1,%2,%3}, [%4];"
        : "=r"(r[0]), "=r"(r[1]), "=r"(r[2]), "=r"(r[3]) : "r"(addr));
}
__device__ __forceinline__ void ldsm_x2t(uint32_t* r, uint32_t addr) {
    asm volatile("ldmatrix.sync.aligned.m8n8.x2.trans.shared.b16 {%0,%1}, [%2];"
        : "=r"(r[0]), "=r"(r[1]) : "r"(addr));
}
// fp16 mma
__device__ __forceinline__ void mma16816h(float* d, const uint32_t* a, const uint32_t* b) {
    asm volatile("mma.sync.aligned.m16n8k16.row.col.f32.f16.f16.f32 "
        "{%0,%1,%2,%3}, {%4,%5,%6,%7}, {%8,%9}, {%0,%1,%2,%3};"
        : "+f"(d[0]), "+f"(d[1]), "+f"(d[2]), "+f"(d[3])
        : "r"(a[0]), "r"(a[1]), "r"(a[2]), "r"(a[3]), "r"(b[0]), "r"(b[1]));
}
__device__ __forceinline__ void split1h(float v, __half& h, __half& l) {
    h = __float2half_rn(v);
    l = __float2half_rn(v - __half2float(h));
}
__device__ __forceinline__ uint32_t packh2(__half2 v) {
    uint32_t u; memcpy(&u, &v, 4); return u;
}

// ---------------- rope table (double-precision sincos, fp32 store) ----------
__global__ void rope_tab_kernel() {
    int idx = blockIdx.x * 256 + threadIdx.x;   // 0..131071
    int s = idx >> 5, i = idx & 31;
    double invf = pow(10000.0, -(2.0 * i) / 64.0);
    double si, co;
    sincos((double)s * invf, &si, &co);
    g_rope[s][i * 2]     = (float)co;
    g_rope[s][i * 2 + 1] = (float)si;
}

// ---------------- fused convert kernel (all 5 inputs, one launch) ----------
// b in [0,4096): x -> fp16 hi/lo
// b in [4096,7168): Wq/Wk/Wv -> fp16 hi (stacked)
// b in [7168,8192): Wo -> fp16 hi
__global__ void cvt_all_kernel(const float* __restrict__ x,
                               const float* __restrict__ Wq,
                               const float* __restrict__ Wk,
                               const float* __restrict__ Wv,
                               const float* __restrict__ Wo) {
    int b = blockIdx.x;
    if (b < 4096) {
        int i = (b * 256 + threadIdx.x) * 4;
        float4 v = *(const float4*)&x[i];
        __half h0, l0, h1, l1, h2, l2, h3, l3;
        split1h(v.x, h0, l0); split1h(v.y, h1, l1);
        split1h(v.z, h2, l2); split1h(v.w, h3, l3);
        __half2 a;
        a.x = h0; a.y = h1; *(uint32_t*)&g_x16h[i]     = packh2(a);
        a.x = h2; a.y = h3; *(uint32_t*)&g_x16h[i + 2] = packh2(a);
        a.x = l0; a.y = l1; *(uint32_t*)&g_x16l[i]     = packh2(a);
        a.x = l2; a.y = l3; *(uint32_t*)&g_x16l[i + 2] = packh2(a);
    } else {
        const float* src; __half* dst; int si, di;
        if (b < 7168) {
            int bb = b - 4096;                 // 0..3071
            int mat = bb >> 10;                // 0..2
            src = (mat == 0) ? Wq : (mat == 1 ? Wk : Wv);
            si = ((bb & 1023) * 256 + threadIdx.x) * 4;
            di = (bb * 256 + threadIdx.x) * 4;
            dst = g_w16;
        } else {
            si = ((b - 7168) * 256 + threadIdx.x) * 4;
            di = si; src = Wo; dst = g_w16o;
        }
        float4 v = *(const float4*)&src[si];
        __half2 a;
        a.x = __float2half_rn(v.x); a.y = __float2half_rn(v.y);
        *(uint32_t*)&dst[di] = packh2(a);
        a.x = __float2half_rn(v.z); a.y = __float2half_rn(v.w);
        *(uint32_t*)&dst[di + 2] = packh2(a);
    }
}

// ---------------- HMMA fp16 NT GEMM ----------------
// C[m,n] = sum_k A[m,k]*B[n,k]; BM=BN=128, BK=64, 128 threads, 4 warps of 64x64.
// WHICH=0: QKV 2-pass (x hi/lo), epilogue applies RoPE and stores fp16.
// WHICH=1: proj 1-pass, epilogue stores fp32 to out.
#define SKB 144                    // smem row stride bytes (72 elems, conflict-free ldsm)
#define GTILE (128 * SKB)          // 18432 B per matrix tile
#define GSTAGE (2 * GTILE)         // A+B
#define GEMM_SMEM (2 * GSTAGE)     // double buffer: 73728
#define QSCALE 0.18033688011112042f   // 0.125 * log2(e)

__device__ __forceinline__ void gemm_issue(int t, uint32_t st,
                                           const char* A, const char* B) {
#pragma unroll
    for (int i = 0; i < 8; i++) {
        int idx = t + i * 128;
        int row = idx >> 3, ch = idx & 7;
        cp_async16(st + row * SKB + ch * 16, A + (size_t)row * (DM * 2) + ch * 16);
        cp_async16(st + GTILE + row * SKB + ch * 16, B + (size_t)row * (DM * 2) + ch * 16);
    }
    CP_COMMIT();
}

template<int WHICH>
__global__ __launch_bounds__(128)
void mma_gemm_kernel(float* __restrict__ outp) {
    constexpr int NCH = (WHICH == 0) ? 32 : 16;
    extern __shared__ char dsm[];
    const uint32_t sbase = smem_u32(dsm);
    const int t = threadIdx.x, lane = t & 31, wid = t >> 5;
    const int nt = blockIdx.x, mt = blockIdx.y;
    const int m0 = mt * 128, n0 = nt * 128;

    const char *pA[2], *pB[2];
    if (WHICH == 0) {
        pA[0] = (const char*)g_x16h; pA[1] = (const char*)g_x16l;
        const char* bh = (const char*)(g_w16 + (size_t)n0 * DM);
        pB[0] = bh; pB[1] = bh;
    } else {
        pA[0] = (const char*)g_a16h; pA[1] = pA[0];
        const char* bh = (const char*)(g_w16o + (size_t)n0 * DM);
        pB[0] = bh; pB[1] = bh;
    }

    float acc[4][8][4];
#pragma unroll
    for (int a = 0; a < 4; a++)
#pragma unroll
        for (int b = 0; b < 8; b++)
#pragma unroll
            for (int c = 0; c < 4; c++) acc[a][b][c] = 0.f;

#pragma unroll
    for (int c = 0; c < 2; c++) {
        int pass = c >> 4, k0 = (c & 15) * 64;
        gemm_issue(t, sbase + (c & 1) * GSTAGE,
                   pA[pass] + (size_t)m0 * (DM * 2) + k0 * 2, pB[pass] + k0 * 2);
    }

    const int wm = wid & 1, wn = wid >> 1;      // 2x2 warps, 64x64 each
    const int q = lane >> 3, r = lane & 7;

    for (int c = 0; c < NCH; c++) {
        if (c + 1 < NCH) { CP_WAIT1(); } else { CP_WAIT0(); }
        __syncthreads();

        const uint32_t sa = sbase + (c & 1) * GSTAGE + (wm * 64) * SKB;
        const uint32_t sb = sbase + (c & 1) * GSTAGE + GTILE + (wn * 64) * SKB;
#pragma unroll
        for (int ks = 0; ks < 4; ks++) {
            uint32_t af[4][4], bf[4][4];
#pragma unroll
            for (int mb = 0; mb < 4; mb++)
                ldsm_x4(af[mb], sa + (mb * 16 + (q & 1) * 8 + r) * SKB
                                   + (ks * 16 + (q >> 1) * 8) * 2);
#pragma unroll
            for (int np = 0; np < 4; np++)
                ldsm_x4(bf[np], sb + (np * 16 + (q >> 1) * 8 + r) * SKB
                                   + (ks * 16 + (q & 1) * 8) * 2);
#pragma unroll
            for (int mb = 0; mb < 4; mb++)
#pragma unroll
                for (int np = 0; np < 4; np++) {
                    mma16816h(acc[mb][np * 2],     af[mb], &bf[np][0]);
                    mma16816h(acc[mb][np * 2 + 1], af[mb], &bf[np][2]);
                }
        }
        __syncthreads();
        if (c + 2 < NCH) {
            int cn = c + 2, pass = cn >> 4, k0 = (cn & 15) * 64;
            gemm_issue(t, sbase + (cn & 1) * GSTAGE,
                       pA[pass] + (size_t)m0 * (DM * 2) + k0 * 2, pB[pass] + k0 * 2);
        }
    }

    const int rr = lane >> 2, c2 = (lane & 3) * 2;
    if (WHICH == 1) {
#pragma unroll
        for (int mb = 0; mb < 4; mb++) {
            int row0 = m0 + wm * 64 + mb * 16 + rr;
#pragma unroll
            for (int nb = 0; nb < 8; nb++) {
                int col = n0 + wn * 64 + nb * 8 + c2;
                *(float2*)&outp[(size_t)row0 * DM + col]       = make_float2(acc[mb][nb][0], acc[mb][nb][1]);
                *(float2*)&outp[(size_t)(row0 + 8) * DM + col] = make_float2(acc[mb][nb][2], acc[mb][nb][3]);
            }
        }
    } else {
        const int mat = nt >> 3;                 // 0=Q 1=K 2=V
        const int ccol = (nt & 7) * 128;
        if (mat == 2) {
            // V: plain fp16 convert
#pragma unroll
            for (int mb = 0; mb < 4; mb++) {
                int row0 = m0 + wm * 64 + mb * 16 + rr;
#pragma unroll
                for (int nb = 0; nb < 8; nb++) {
                    int col = ccol + wn * 64 + nb * 8 + c2;
                    *(uint32_t*)&g_vh[(size_t)row0 * DM + col] =
                        packh2(__floats2half2_rn(acc[mb][nb][0], acc[mb][nb][1]));
                    *(uint32_t*)&g_vh[(size_t)(row0 + 8) * DM + col] =
                        packh2(__floats2half2_rn(acc[mb][nb][2], acc[mb][nb][3]));
                }
            }
        } else {
            // Q/K: apply RoPE in fp32, store fp16 (Q pre-scaled by log2e/8).
            // Warp 64-col span = one head; pair (i, i+32) = (nb, nb+4).
            __half* dst = (mat == 0) ? g_qh : g_kh;
            const float scale = (mat == 0) ? QSCALE : 1.f;
#pragma unroll
            for (int mb = 0; mb < 4; mb++) {
                int row0 = m0 + wm * 64 + mb * 16 + rr;
#pragma unroll
                for (int nb = 0; nb < 4; nb++) {
                    int i = nb * 8 + c2;                      // head-local col (0..31)
                    float4 t0 = *(float4*)&g_rope[row0][i * 2];        // cs_i sn_i cs_i1 sn_i1
                    float4 t1 = *(float4*)&g_rope[row0 + 8][i * 2];
                    int col_lo = ccol + wn * 64 + nb * 8 + c2;
                    int col_hi = col_lo + 32;
                    // row0, cols i / i+1
                    {
                        float a0 = acc[mb][nb][0], b0 = acc[mb][nb + 4][0];
                        float a1 = acc[mb][nb][1], b1 = acc[mb][nb + 4][1];
                        float lo0 = (a0 * t0.x - b0 * t0.y) * scale;
                        float hi0 = (b0 * t0.x + a0 * t0.y) * scale;
                        float lo1 = (a1 * t0.z - b1 * t0.w) * scale;
                        float hi1 = (b1 * t0.z + a1 * t0.w) * scale;
                        *(uint32_t*)&dst[(size_t)row0 * DM + col_lo] = packh2(__floats2half2_rn(lo0, lo1));
                        *(uint32_t*)&dst[(size_t)row0 * DM + col_hi] = packh2(__floats2half2_rn(hi0, hi1));
                    }
                    // row0+8
                    {
                        float a0 = acc[mb][nb][2], b0 = acc[mb][nb + 4][2];
                        float a1 = acc[mb][nb][3], b1 = acc[mb][nb + 4][3];
                        float lo0 = (a0 * t1.x - b0 * t1.y) * scale;
                        float hi0 = (b0 * t1.x + a0 * t1.y) * scale;
                        float lo1 = (a1 * t1.z - b1 * t1.w) * scale;
                        float hi1 = (b1 * t1.z + a1 * t1.w) * scale;
                        *(uint32_t*)&dst[(size_t)(row0 + 8) * DM + col_lo] = packh2(__floats2half2_rn(lo0, lo1));
                        *(uint32_t*)&dst[(size_t)(row0 + 8) * DM + col_hi] = packh2(__floats2half2_rn(hi0, hi1));
                    }
                }
            }
        }
    }
}

// ---------------- Flash attention: fp16 HMMA, exp2-domain softmax -----------
// CTA = (q-tile 128 rows, head). 256 thr / 8 warps; warp = 16 q-rows x full 64 kv.
// V tile rows are 72 halves wide; cols 64..71 hold {1,0,...,0} -> row-sum via MMA.
#define F_STG 18432            // stage s at F_STG + s*F_STGSZ: Kh, Vh (9216 each)
#define F_T   9216
#define F_STGSZ 18432
#define FLASH_SMEM (18432 + 2 * F_STGSZ)   // 55296

__device__ __forceinline__ void flash_issue_kv(int t, uint32_t stg, int kbase, int h) {
    const size_t rowoff = (size_t)kbase * DM + h * 64;
    const __half* srcs[2] = {g_kh + rowoff, g_vh + rowoff};
#pragma unroll
    for (int i = 0; i < 4; i++) {
        int idx = t + i * 256;              // 0..1023
        int mat = idx >> 9;                 // 0..1
        int rem = idx & 511;
        int row = rem >> 3, ch = rem & 7;
        cp_async16(stg + mat * F_T + row * SKB + ch * 16,
                   (const char*)srcs[mat] + (size_t)row * (DM * 2) + ch * 16);
    }
    CP_COMMIT();
}

__global__ __launch_bounds__(256)
void flash_kernel() {
    extern __shared__ char dsm[];
    const uint32_t sbase = smem_u32(dsm);
    const int t = threadIdx.x, lane = t & 31, wid = t >> 5;
    const int h = blockIdx.y;
    const int qt = (int)gridDim.x - 1 - (int)blockIdx.x;   // heavy first
    const int qbase = qt * 128;
    const int ntiles = 2 * qt + 2;

    // Q load + kv tile0 (one group), then kv tile1
    {
        const size_t rowoff = (size_t)qbase * DM + h * 64;
#pragma unroll
        for (int i = 0; i < 4; i++) {
            int idx = t + i * 256;           // 0..1023
            int row = idx >> 3, ch = idx & 7;
            cp_async16(sbase + row * SKB + ch * 16,
                       (const char*)(g_qh + rowoff) + (size_t)row * (DM * 2) + ch * 16);
        }
        flash_issue_kv(t, sbase + F_STG, 0, h);            // commits Q + tile0
        flash_issue_kv(t, sbase + F_STG + F_STGSZ, 64, h); // tile 1
    }

    // Ones-column pad for both V stage buffers (bytes 128..143 of each V row;
    // cp.async only writes bytes 0..127, so this persists across stage reuse).
    if (t < 128) {
        int buf = t >> 6, row = t & 63;
        uint32_t addr = sbase + F_STG + buf * F_STGSZ + F_T + row * SKB + 128;
        uint4 ones = make_uint4(0x00003C00u, 0u, 0u, 0u);  // half {1,0,0,0,0,0,0,0}
        *(uint4*)(dsm + (addr - sbase)) = ones;
    }

    CP_WAIT1();          // Q + tile0 ready
    __syncthreads();

    // preload Q fragments (persistent)
    const int q = lane >> 3, r = lane & 7;
    const int l16 = lane & 15;
    uint32_t qf[4][4];
#pragma unroll
    for (int ks = 0; ks < 4; ks++) {
        uint32_t ro = (wid * 16 + (q & 1) * 8 + r) * SKB + (ks * 16 + (q >> 1) * 8) * 2;
        ldsm_x4(qf[ks], sbase + ro);
    }
    // hoisted ones-column B fragment (identical for all tiles / k-steps)
    uint32_t bs_ones[2];
    ldsm_x2t(bs_ones, sbase + F_STG + F_T + l16 * SKB + 128);

    float o[8][4], o_sum[4];
#pragma unroll
    for (int a = 0; a < 8; a++)
#pragma unroll
        for (int b = 0; b < 4; b++) o[a][b] = 0.f;
#pragma unroll
    for (int b = 0; b < 4; b++) o_sum[b] = 0.f;
    float m0r = -1e30f, m1r = -1e30f;

    const int rr = lane >> 2, c2 = (lane & 3) * 2;
    const int qlo = qbase + wid * 16;
    const int qr0 = qlo + rr, qr1 = qr0 + 8;

    for (int kt = 0; kt < ntiles; kt++) {
        const uint32_t stg = sbase + F_STG + (kt & 1) * F_STGSZ;

        if (kt * 64 <= qlo + 15) {     // warp tile not fully masked
            float s[8][4];
#pragma unroll
            for (int a = 0; a < 8; a++)
#pragma unroll
                for (int b = 0; b < 4; b++) s[a][b] = 0.f;

            // S = Q * K (logits in log2 domain; Q pre-scaled by log2e/8)
#pragma unroll
            for (int ks = 0; ks < 4; ks++) {
#pragma unroll
                for (int np = 0; np < 4; np++) {
                    uint32_t kf[4];
                    uint32_t ro = (np * 16 + (q >> 1) * 8 + r) * SKB + (ks * 16 + (q & 1) * 8) * 2;
                    ldsm_x4(kf, stg + 0 * F_T + ro);
                    mma16816h(s[np * 2],     qf[ks], &kf[0]);
                    mma16816h(s[np * 2 + 1], qf[ks], &kf[2]);
                }
            }

            // causal mask (diagonal-straddling tiles only)
            if (kt * 64 + 63 > qlo) {
#pragma unroll
                for (int nb = 0; nb < 8; nb++) {
                    int kc = kt * 64 + nb * 8 + c2;
                    if (kc     > qr0) s[nb][0] = -1e30f;
                    if (kc + 1 > qr0) s[nb][1] = -1e30f;
                    if (kc     > qr1) s[nb][2] = -1e30f;
                    if (kc + 1 > qr1) s[nb][3] = -1e30f;
                }
            }

            // online max (log2 domain)
            float mx0 = -1e30f, mx1 = -1e30f;
#pragma unroll
            for (int nb = 0; nb < 8; nb++) {
                mx0 = fmaxf(mx0, fmaxf(s[nb][0], s[nb][1]));
                mx1 = fmaxf(mx1, fmaxf(s[nb][2], s[nb][3]));
            }
            mx0 = fmaxf(mx0, __shfl_xor_sync(0xffffffffu, mx0, 1));
            mx0 = fmaxf(mx0, __shfl_xor_sync(0xffffffffu, mx0, 2));
            mx1 = fmaxf(mx1, __shfl_xor_sync(0xffffffffu, mx1, 1));
            mx1 = fmaxf(mx1, __shfl_xor_sync(0xffffffffu, mx1, 2));
            float mn0 = fmaxf(m0r, mx0), mn1 = fmaxf(m1r, mx1);
            float al0 = exp2f(m0r - mn0), al1 = exp2f(m1r - mn1);
            m0r = mn0;  m1r = mn1;
#pragma unroll
            for (int nb = 0; nb < 8; nb++) {
                o[nb][0] *= al0; o[nb][1] *= al0;
                o[nb][2] *= al1; o[nb][3] *= al1;
            }
            o_sum[0] *= al0; o_sum[1] *= al0;
            o_sum[2] *= al1; o_sum[3] *= al1;

            // P = exp2(s - m) computed in fp16x2; PV (+ ones-column row sum)
#pragma unroll
            for (int ks = 0; ks < 4; ks++) {
                uint32_t ph[4];
#pragma unroll
                for (int hf = 0; hf < 2; hf++) {
                    int nb = 2 * ks + hf;
                    __half2 e0 = h2exp2(__floats2half2_rn(s[nb][0] - mn0, s[nb][1] - mn0));
                    __half2 e1 = h2exp2(__floats2half2_rn(s[nb][2] - mn1, s[nb][3] - mn1));
                    ph[hf * 2]     = packh2(e0);
                    ph[hf * 2 + 1] = packh2(e1);
                }
#pragma unroll
                for (int dp = 0; dp < 4; dp++) {
                    uint32_t vf[4];
                    uint32_t ro = (ks * 16 + (q & 1) * 8 + r) * SKB + (dp * 16 + (q >> 1) * 8) * 2;
                    ldsm_x4t(vf, stg + 1 * F_T + ro);
                    mma16816h(o[dp * 2],     ph, &vf[0]);
                    mma16816h(o[dp * 2 + 1], ph, &vf[2]);
                }
                mma16816h(o_sum, ph, bs_ones);
            }
        }

        __syncthreads();          // done reading this stage
        if (kt + 2 < ntiles)
            flash_issue_kv(t, sbase + F_STG + (kt & 1) * F_STGSZ, (kt + 2) * 64, h);
        if (kt + 1 < ntiles) {
            if (kt + 2 < ntiles) { CP_WAIT1(); } else { CP_WAIT0(); }
            __syncthreads();      // tile kt+1 data visible to all
        }
    }

    // epilogue: l lives in o_sum col 0 (lanes with lane&3==0); broadcast in quad
    float l0 = __shfl_sync(0xffffffffu, o_sum[0], lane & 0x1C);
    float l1 = __shfl_sync(0xffffffffu, o_sum[2], lane & 0x1C);
    float inv0 = 1.f / l0, inv1 = 1.f / l1;
#pragma unroll
    for (int nb = 0; nb < 8; nb++) {
        int col = h * 64 + nb * 8 + c2;
        *(uint32_t*)&g_a16h[(size_t)qr0 * DM + col] =
            packh2(__floats2half2_rn(o[nb][0] * inv0, o[nb][1] * inv0));
        *(uint32_t*)&g_a16h[(size_t)qr1 * DM + col] =
            packh2(__floats2half2_rn(o[nb][2] * inv1, o[nb][3] * inv1));
    }
}

// ---------------- launch ----------------
extern "C" void kernel_launch(void* const* d_in, const int* in_sizes, int n_in,
                              void* d_out, int out_size) {
    const float* x  = (const float*)d_in[0];
    const float* Wq = (const float*)d_in[1];
    const float* Wk = (const float*)d_in[2];
    const float* Wv = (const float*)d_in[3];
    const float* Wo = (const float*)d_in[4];
    float* out = (float*)d_out;

    cudaFuncSetAttribute(mma_gemm_kernel<0>, cudaFuncAttributeMaxDynamicSharedMemorySize, GEMM_SMEM);
    cudaFuncSetAttribute(mma_gemm_kernel<1>, cudaFuncAttributeMaxDynamicSharedMemorySize, GEMM_SMEM);
    cudaFuncSetAttribute(flash_kernel,       cudaFuncAttributeMaxDynamicSharedMemorySize, FLASH_SMEM);

    rope_tab_kernel<<<512, 256>>>();
    cvt_all_kernel<<<8192, 256>>>(x, Wq, Wk, Wv, Wo);

    mma_gemm_kernel<0><<<dim3(3 * DM / 128, SEQ / 128), 128, GEMM_SMEM>>>(nullptr);

    flash_kernel<<<dim3(SEQ / 128, NH), 256, FLASH_SMEM>>>();

    mma_gemm_kernel<1><<<dim3(DM / 128, SEQ / 128), 128, GEMM_SMEM>>>(out);
}

// round 10
// speedup vs baseline: 2.4096x; 1.2417x over previous
#include <cuda_runtime.h>
#include <cuda_fp16.h>
#include <math.h>
#include <stdint.h>

// Problem constants
#define SEQ   4096
#define DM    1024
#define NH    16
#define DH    64

// ---------------- scratch (no allocations allowed) ----------------
// QKV GEMM operands (fp16, 1-pass): x, W (Wq,Wk,Wv stacked rows)
__device__ __half g_x16h[SEQ * DM];
__device__ __half g_w16[3 * DM * DM];
// proj GEMM operands (fp16, 1-pass)
__device__ __half g_w16o[DM * DM];
__device__ __half g_a16h[SEQ * DM];        // attention out (fp16)

// flash operands (fp16), written directly by the QKV epilogue
__device__ __half g_qh[SEQ * DM];   // roped Q, pre-scaled by (1/8)*log2e
__device__ __half g_kh[SEQ * DM];   // roped K
__device__ __half g_vh[SEQ * DM];   // V

// rope table: [s][i*2]=cos, [i*2+1]=sin  (i = 0..31)
__device__ float g_rope[SEQ][64];

// ---------------- low-level helpers ----------------
__device__ __forceinline__ uint32_t smem_u32(const void* p) {
    uint32_t a;
    asm("{ .reg .u64 t; cvta.to.shared.u64 t, %1; cvt.u32.u64 %0, t; }" : "=r"(a) : "l"(p));
    return a;
}
__device__ __forceinline__ void cp_async16(uint32_t sa, const void* ga) {
    asm volatile("cp.async.cg.shared.global [%0], [%1], 16;" :: "r"(sa), "l"(ga));
}
#define CP_COMMIT() asm volatile("cp.async.commit_group;" ::: "memory")
#define CP_WAIT1()  asm volatile("cp.async.wait_group 1;" ::: "memory")
#define CP_WAIT0()  asm volatile("cp.async.wait_group 0;" ::: "memory")

__device__ __forceinline__ void ldsm_x4(uint32_t* r, uint32_t addr) {
    asm volatile("ldmatrix.sync.aligned.m8n8.x4.shared.b16 {%0,%1,%2,%3}, [%4];"
        : "=r"(r[0]), "=r"(r[1]), "=r"(r[2]), "=r"(r[3]) : "r"(addr));
}
__device__ __forceinline__ void ldsm_x4t(uint32_t* r, uint32_t addr) {
    asm volatile("ldmatrix.sync.aligned.m8n8.x4.trans.shared.b16 {%0,%1,%2,%3}, [%4];"
        : "=r"(r[0]), "=r"(r[1]), "=r"(r[2]), "=r"(r[3]) : "r"(addr));
}
__device__ __forceinline__ void ldsm_x2t(uint32_t* r, uint32_t addr) {
    asm volatile("ldmatrix.sync.aligned.m8n8.x2.trans.shared.b16 {%0,%1}, [%2];"
        : "=r"(r[0]), "=r"(r[1]) : "r"(addr));
}
// fp16 mma
__device__ __forceinline__ void mma16816h(float* d, const uint32_t* a, const uint32_t* b) {
    asm volatile("mma.sync.aligned.m16n8k16.row.col.f32.f16.f16.f32 "
        "{%0,%1,%2,%3}, {%4,%5,%6,%7}, {%8,%9}, {%0,%1,%2,%3};"
        : "+f"(d[0]), "+f"(d[1]), "+f"(d[2]), "+f"(d[3])
        : "r"(a[0]), "r"(a[1]), "r"(a[2]), "r"(a[3]), "r"(b[0]), "r"(b[1]));
}
__device__ __forceinline__ uint32_t packh2(__half2 v) {
    uint32_t u; memcpy(&u, &v, 4); return u;
}

// ---------------- rope table (double-precision sincos, fp32 store) ----------
__global__ void rope_tab_kernel() {
    int idx = blockIdx.x * 256 + threadIdx.x;   // 0..131071
    int s = idx >> 5, i = idx & 31;
    double invf = pow(10000.0, -(2.0 * i) / 64.0);
    double si, co;
    sincos((double)s * invf, &si, &co);
    g_rope[s][i * 2]     = (float)co;
    g_rope[s][i * 2 + 1] = (float)si;
}

// ---------------- fused convert kernel (all 5 inputs, one launch) ----------
// b in [0,4096): x; [4096,7168): Wq/Wk/Wv (stacked); [7168,8192): Wo.
__global__ void cvt_all_kernel(const float* __restrict__ x,
                               const float* __restrict__ Wq,
                               const float* __restrict__ Wk,
                               const float* __restrict__ Wv,
                               const float* __restrict__ Wo) {
    int b = blockIdx.x;
    const float* src; __half* dst; int si, di;
    if (b < 4096) {
        si = (b * 256 + threadIdx.x) * 4;
        di = si; src = x; dst = g_x16h;
    } else if (b < 7168) {
        int bb = b - 4096;                 // 0..3071
        int mat = bb >> 10;                // 0..2
        src = (mat == 0) ? Wq : (mat == 1 ? Wk : Wv);
        si = ((bb & 1023) * 256 + threadIdx.x) * 4;
        di = (bb * 256 + threadIdx.x) * 4;
        dst = g_w16;
    } else {
        si = ((b - 7168) * 256 + threadIdx.x) * 4;
        di = si; src = Wo; dst = g_w16o;
    }
    float4 v = *(const float4*)&src[si];
    *(uint32_t*)&dst[di]     = packh2(__floats2half2_rn(v.x, v.y));
    *(uint32_t*)&dst[di + 2] = packh2(__floats2half2_rn(v.z, v.w));
}

// ---------------- HMMA fp16 1-pass NT GEMM ----------------
// C[m,n] = sum_k A[m,k]*B[n,k]; BM=BN=128, BK=64, 128 threads, 4 warps of 64x64.
// WHICH=0: QKV; epilogue applies RoPE and stores fp16. WHICH=1: proj -> fp32 out.
#define SKB 144                    // smem row stride bytes (72 elems, conflict-free ldsm)
#define GTILE (128 * SKB)          // 18432 B per matrix tile
#define GSTAGE (2 * GTILE)         // A+B
#define GEMM_SMEM (2 * GSTAGE)     // double buffer: 73728
#define QSCALE 0.18033688011112042f   // 0.125 * log2(e)

__device__ __forceinline__ void gemm_issue(int t, uint32_t st,
                                           const char* A, const char* B) {
#pragma unroll
    for (int i = 0; i < 8; i++) {
        int idx = t + i * 128;
        int row = idx >> 3, ch = idx & 7;
        cp_async16(st + row * SKB + ch * 16, A + (size_t)row * (DM * 2) + ch * 16);
        cp_async16(st + GTILE + row * SKB + ch * 16, B + (size_t)row * (DM * 2) + ch * 16);
    }
    CP_COMMIT();
}

template<int WHICH>
__global__ __launch_bounds__(128)
void mma_gemm_kernel(float* __restrict__ outp) {
    constexpr int NCH = 16;        // 1 pass x 16 chunks of BK=64
    extern __shared__ char dsm[];
    const uint32_t sbase = smem_u32(dsm);
    const int t = threadIdx.x, lane = t & 31, wid = t >> 5;
    const int nt = blockIdx.x, mt = blockIdx.y;
    const int m0 = mt * 128, n0 = nt * 128;

    const char* pA = (WHICH == 0) ? (const char*)g_x16h : (const char*)g_a16h;
    const char* pB = (WHICH == 0) ? (const char*)(g_w16 + (size_t)n0 * DM)
                                  : (const char*)(g_w16o + (size_t)n0 * DM);

    float acc[4][8][4];
#pragma unroll
    for (int a = 0; a < 4; a++)
#pragma unroll
        for (int b = 0; b < 8; b++)
#pragma unroll
            for (int c = 0; c < 4; c++) acc[a][b][c] = 0.f;

#pragma unroll
    for (int c = 0; c < 2; c++) {
        int k0 = c * 64;
        gemm_issue(t, sbase + (c & 1) * GSTAGE,
                   pA + (size_t)m0 * (DM * 2) + k0 * 2, pB + k0 * 2);
    }

    const int wm = wid & 1, wn = wid >> 1;      // 2x2 warps, 64x64 each
    const int q = lane >> 3, r = lane & 7;

    for (int c = 0; c < NCH; c++) {
        if (c + 1 < NCH) { CP_WAIT1(); } else { CP_WAIT0(); }
        __syncthreads();

        const uint32_t sa = sbase + (c & 1) * GSTAGE + (wm * 64) * SKB;
        const uint32_t sb = sbase + (c & 1) * GSTAGE + GTILE + (wn * 64) * SKB;
#pragma unroll
        for (int ks = 0; ks < 4; ks++) {
            uint32_t af[4][4], bf[4][4];
#pragma unroll
            for (int mb = 0; mb < 4; mb++)
                ldsm_x4(af[mb], sa + (mb * 16 + (q & 1) * 8 + r) * SKB
                                   + (ks * 16 + (q >> 1) * 8) * 2);
#pragma unroll
            for (int np = 0; np < 4; np++)
                ldsm_x4(bf[np], sb + (np * 16 + (q >> 1) * 8 + r) * SKB
                                   + (ks * 16 + (q & 1) * 8) * 2);
#pragma unroll
            for (int mb = 0; mb < 4; mb++)
#pragma unroll
                for (int np = 0; np < 4; np++) {
                    mma16816h(acc[mb][np * 2],     af[mb], &bf[np][0]);
                    mma16816h(acc[mb][np * 2 + 1], af[mb], &bf[np][2]);
                }
        }
        __syncthreads();
        if (c + 2 < NCH) {
            int cn = c + 2, k0 = cn * 64;
            gemm_issue(t, sbase + (cn & 1) * GSTAGE,
                       pA + (size_t)m0 * (DM * 2) + k0 * 2, pB + k0 * 2);
        }
    }

    const int rr = lane >> 2, c2 = (lane & 3) * 2;
    if (WHICH == 1) {
#pragma unroll
        for (int mb = 0; mb < 4; mb++) {
            int row0 = m0 + wm * 64 + mb * 16 + rr;
#pragma unroll
            for (int nb = 0; nb < 8; nb++) {
                int col = n0 + wn * 64 + nb * 8 + c2;
                *(float2*)&outp[(size_t)row0 * DM + col]       = make_float2(acc[mb][nb][0], acc[mb][nb][1]);
                *(float2*)&outp[(size_t)(row0 + 8) * DM + col] = make_float2(acc[mb][nb][2], acc[mb][nb][3]);
            }
        }
    } else {
        const int mat = nt >> 3;                 // 0=Q 1=K 2=V
        const int ccol = (nt & 7) * 128;
        if (mat == 2) {
            // V: plain fp16 convert
#pragma unroll
            for (int mb = 0; mb < 4; mb++) {
                int row0 = m0 + wm * 64 + mb * 16 + rr;
#pragma unroll
                for (int nb = 0; nb < 8; nb++) {
                    int col = ccol + wn * 64 + nb * 8 + c2;
                    *(uint32_t*)&g_vh[(size_t)row0 * DM + col] =
                        packh2(__floats2half2_rn(acc[mb][nb][0], acc[mb][nb][1]));
                    *(uint32_t*)&g_vh[(size_t)(row0 + 8) * DM + col] =
                        packh2(__floats2half2_rn(acc[mb][nb][2], acc[mb][nb][3]));
                }
            }
        } else {
            // Q/K: apply RoPE in fp32, store fp16 (Q pre-scaled by log2e/8).
            // Warp 64-col span = one head; pair (i, i+32) = (nb, nb+4).
            __half* dst = (mat == 0) ? g_qh : g_kh;
            const float scale = (mat == 0) ? QSCALE : 1.f;
#pragma unroll
            for (int mb = 0; mb < 4; mb++) {
                int row0 = m0 + wm * 64 + mb * 16 + rr;
#pragma unroll
                for (int nb = 0; nb < 4; nb++) {
                    int i = nb * 8 + c2;                      // head-local col (0..31)
                    float4 t0 = *(float4*)&g_rope[row0][i * 2];        // cs_i sn_i cs_i1 sn_i1
                    float4 t1 = *(float4*)&g_rope[row0 + 8][i * 2];
                    int col_lo = ccol + wn * 64 + nb * 8 + c2;
                    int col_hi = col_lo + 32;
                    // row0, cols i / i+1
                    {
                        float a0 = acc[mb][nb][0], b0 = acc[mb][nb + 4][0];
                        float a1 = acc[mb][nb][1], b1 = acc[mb][nb + 4][1];
                        float lo0 = (a0 * t0.x - b0 * t0.y) * scale;
                        float hi0 = (b0 * t0.x + a0 * t0.y) * scale;
                        float lo1 = (a1 * t0.z - b1 * t0.w) * scale;
                        float hi1 = (b1 * t0.z + a1 * t0.w) * scale;
                        *(uint32_t*)&dst[(size_t)row0 * DM + col_lo] = packh2(__floats2half2_rn(lo0, lo1));
                        *(uint32_t*)&dst[(size_t)row0 * DM + col_hi] = packh2(__floats2half2_rn(hi0, hi1));
                    }
                    // row0+8
                    {
                        float a0 = acc[mb][nb][2], b0 = acc[mb][nb + 4][2];
                        float a1 = acc[mb][nb][3], b1 = acc[mb][nb + 4][3];
                        float lo0 = (a0 * t1.x - b0 * t1.y) * scale;
                        float hi0 = (b0 * t1.x + a0 * t1.y) * scale;
                        float lo1 = (a1 * t1.z - b1 * t1.w) * scale;
                        float hi1 = (b1 * t1.z + a1 * t1.w) * scale;
                        *(uint32_t*)&dst[(size_t)(row0 + 8) * DM + col_lo] = packh2(__floats2half2_rn(lo0, lo1));
                        *(uint32_t*)&dst[(size_t)(row0 + 8) * DM + col_hi] = packh2(__floats2half2_rn(hi0, hi1));
                    }
                }
            }
        }
    }
}

// ---------------- Flash attention: fp16 HMMA, exp2-domain softmax -----------
// CTA = (q-tile 128 rows, head). 256 thr / 8 warps; warp = 16 q-rows x full 64 kv.
// V tile rows are 72 halves wide; cols 64..71 hold {1,0,...,0} -> row-sum via MMA.
#define F_STG 18432            // stage s at F_STG + s*F_STGSZ: Kh, Vh (9216 each)
#define F_T   9216
#define F_STGSZ 18432
#define FLASH_SMEM (18432 + 2 * F_STGSZ)   // 55296

__device__ __forceinline__ void flash_issue_kv(int t, uint32_t stg, int kbase, int h) {
    const size_t rowoff = (size_t)kbase * DM + h * 64;
    const __half* srcs[2] = {g_kh + rowoff, g_vh + rowoff};
#pragma unroll
    for (int i = 0; i < 4; i++) {
        int idx = t + i * 256;              // 0..1023
        int mat = idx >> 9;                 // 0..1
        int rem = idx & 511;
        int row = rem >> 3, ch = rem & 7;
        cp_async16(stg + mat * F_T + row * SKB + ch * 16,
                   (const char*)srcs[mat] + (size_t)row * (DM * 2) + ch * 16);
    }
    CP_COMMIT();
}

__global__ __launch_bounds__(256)
void flash_kernel() {
    extern __shared__ char dsm[];
    const uint32_t sbase = smem_u32(dsm);
    const int t = threadIdx.x, lane = t & 31, wid = t >> 5;
    const int h = blockIdx.y;
    const int qt = (int)gridDim.x - 1 - (int)blockIdx.x;   // heavy first
    const int qbase = qt * 128;
    const int ntiles = 2 * qt + 2;

    // Q load + kv tile0 (one group), then kv tile1
    {
        const size_t rowoff = (size_t)qbase * DM + h * 64;
#pragma unroll
        for (int i = 0; i < 4; i++) {
            int idx = t + i * 256;           // 0..1023
            int row = idx >> 3, ch = idx & 7;
            cp_async16(sbase + row * SKB + ch * 16,
                       (const char*)(g_qh + rowoff) + (size_t)row * (DM * 2) + ch * 16);
        }
        flash_issue_kv(t, sbase + F_STG, 0, h);            // commits Q + tile0
        flash_issue_kv(t, sbase + F_STG + F_STGSZ, 64, h); // tile 1
    }

    // Ones-column pad for both V stage buffers (bytes 128..143 of each V row;
    // cp.async only writes bytes 0..127, so this persists across stage reuse).
    if (t < 128) {
        int buf = t >> 6, row = t & 63;
        uint32_t addr = sbase + F_STG + buf * F_STGSZ + F_T + row * SKB + 128;
        uint4 ones = make_uint4(0x00003C00u, 0u, 0u, 0u);  // half {1,0,0,0,0,0,0,0}
        *(uint4*)(dsm + (addr - sbase)) = ones;
    }

    CP_WAIT1();          // Q + tile0 ready
    __syncthreads();

    // preload Q fragments (persistent)
    const int q = lane >> 3, r = lane & 7;
    const int l16 = lane & 15;
    uint32_t qf[4][4];
#pragma unroll
    for (int ks = 0; ks < 4; ks++) {
        uint32_t ro = (wid * 16 + (q & 1) * 8 + r) * SKB + (ks * 16 + (q >> 1) * 8) * 2;
        ldsm_x4(qf[ks], sbase + ro);
    }
    // hoisted ones-column B fragment (identical for all tiles / k-steps)
    uint32_t bs_ones[2];
    ldsm_x2t(bs_ones, sbase + F_STG + F_T + l16 * SKB + 128);

    float o[8][4], o_sum[4];
#pragma unroll
    for (int a = 0; a < 8; a++)
#pragma unroll
        for (int b = 0; b < 4; b++) o[a][b] = 0.f;
#pragma unroll
    for (int b = 0; b < 4; b++) o_sum[b] = 0.f;
    float m0r = -1e30f, m1r = -1e30f;

    const int rr = lane >> 2, c2 = (lane & 3) * 2;
    const int qlo = qbase + wid * 16;
    const int qr0 = qlo + rr, qr1 = qr0 + 8;

    for (int kt = 0; kt < ntiles; kt++) {
        const uint32_t stg = sbase + F_STG + (kt & 1) * F_STGSZ;

        if (kt * 64 <= qlo + 15) {     // warp tile not fully masked
            float s[8][4];
#pragma unroll
            for (int a = 0; a < 8; a++)
#pragma unroll
                for (int b = 0; b < 4; b++) s[a][b] = 0.f;

            // S = Q * K (logits in log2 domain; Q pre-scaled by log2e/8)
#pragma unroll
            for (int ks = 0; ks < 4; ks++) {
#pragma unroll
                for (int np = 0; np < 4; np++) {
                    uint32_t kf[4];
                    uint32_t ro = (np * 16 + (q >> 1) * 8 + r) * SKB + (ks * 16 + (q & 1) * 8) * 2;
                    ldsm_x4(kf, stg + 0 * F_T + ro);
                    mma16816h(s[np * 2],     qf[ks], &kf[0]);
                    mma16816h(s[np * 2 + 1], qf[ks], &kf[2]);
                }
            }

            // causal mask (diagonal-straddling tiles only)
            if (kt * 64 + 63 > qlo) {
#pragma unroll
                for (int nb = 0; nb < 8; nb++) {
                    int kc = kt * 64 + nb * 8 + c2;
                    if (kc     > qr0) s[nb][0] = -1e30f;
                    if (kc + 1 > qr0) s[nb][1] = -1e30f;
                    if (kc     > qr1) s[nb][2] = -1e30f;
                    if (kc + 1 > qr1) s[nb][3] = -1e30f;
                }
            }

            // online max (log2 domain)
            float mx0 = -1e30f, mx1 = -1e30f;
#pragma unroll
            for (int nb = 0; nb < 8; nb++) {
                mx0 = fmaxf(mx0, fmaxf(s[nb][0], s[nb][1]));
                mx1 = fmaxf(mx1, fmaxf(s[nb][2], s[nb][3]));
            }
            mx0 = fmaxf(mx0, __shfl_xor_sync(0xffffffffu, mx0, 1));
            mx0 = fmaxf(mx0, __shfl_xor_sync(0xffffffffu, mx0, 2));
            mx1 = fmaxf(mx1, __shfl_xor_sync(0xffffffffu, mx1, 1));
            mx1 = fmaxf(mx1, __shfl_xor_sync(0xffffffffu, mx1, 2));
            float mn0 = fmaxf(m0r, mx0), mn1 = fmaxf(m1r, mx1);
            float al0 = exp2f(m0r - mn0), al1 = exp2f(m1r - mn1);
            m0r = mn0;  m1r = mn1;
#pragma unroll
            for (int nb = 0; nb < 8; nb++) {
                o[nb][0] *= al0; o[nb][1] *= al0;
                o[nb][2] *= al1; o[nb][3] *= al1;
            }
            o_sum[0] *= al0; o_sum[1] *= al0;
            o_sum[2] *= al1; o_sum[3] *= al1;

            // P = exp2(s - m) computed in fp16x2; PV (+ ones-column row sum)
#pragma unroll
            for (int ks = 0; ks < 4; ks++) {
                uint32_t ph[4];
#pragma unroll
                for (int hf = 0; hf < 2; hf++) {
                    int nb = 2 * ks + hf;
                    __half2 e0 = h2exp2(__floats2half2_rn(s[nb][0] - mn0, s[nb][1] - mn0));
                    __half2 e1 = h2exp2(__floats2half2_rn(s[nb][2] - mn1, s[nb][3] - mn1));
                    ph[hf * 2]     = packh2(e0);
                    ph[hf * 2 + 1] = packh2(e1);
                }
#pragma unroll
                for (int dp = 0; dp < 4; dp++) {
                    uint32_t vf[4];
                    uint32_t ro = (ks * 16 + (q & 1) * 8 + r) * SKB + (dp * 16 + (q >> 1) * 8) * 2;
                    ldsm_x4t(vf, stg + 1 * F_T + ro);
                    mma16816h(o[dp * 2],     ph, &vf[0]);
                    mma16816h(o[dp * 2 + 1], ph, &vf[2]);
                }
                mma16816h(o_sum, ph, bs_ones);
            }
        }

        __syncthreads();          // done reading this stage
        if (kt + 2 < ntiles)
            flash_issue_kv(t, sbase + F_STG + (kt & 1) * F_STGSZ, (kt + 2) * 64, h);
        if (kt + 1 < ntiles) {
            if (kt + 2 < ntiles) { CP_WAIT1(); } else { CP_WAIT0(); }
            __syncthreads();      // tile kt+1 data visible to all
        }
    }

    // epilogue: l lives in o_sum col 0 (lanes with lane&3==0); broadcast in quad
    float l0 = __shfl_sync(0xffffffffu, o_sum[0], lane & 0x1C);
    float l1 = __shfl_sync(0xffffffffu, o_sum[2], lane & 0x1C);
    float inv0 = 1.f / l0, inv1 = 1.f / l1;
#pragma unroll
    for (int nb = 0; nb < 8; nb++) {
        int col = h * 64 + nb * 8 + c2;
        *(uint32_t*)&g_a16h[(size_t)qr0 * DM + col] =
            packh2(__floats2half2_rn(o[nb][0] * inv0, o[nb][1] * inv0));
        *(uint32_t*)&g_a16h[(size_t)qr1 * DM + col] =
            packh2(__floats2half2_rn(o[nb][2] * inv1, o[nb][3] * inv1));
    }
}

// ---------------- launch ----------------
extern "C" void kernel_launch(void* const* d_in, const int* in_sizes, int n_in,
                              void* d_out, int out_size) {
    const float* x  = (const float*)d_in[0];
    const float* Wq = (const float*)d_in[1];
    const float* Wk = (const float*)d_in[2];
    const float* Wv = (const float*)d_in[3];
    const float* Wo = (const float*)d_in[4];
    float* out = (float*)d_out;

    cudaFuncSetAttribute(mma_gemm_kernel<0>, cudaFuncAttributeMaxDynamicSharedMemorySize, GEMM_SMEM);
    cudaFuncSetAttribute(mma_gemm_kernel<1>, cudaFuncAttributeMaxDynamicSharedMemorySize, GEMM_SMEM);
    cudaFuncSetAttribute(flash_kernel,       cudaFuncAttributeMaxDynamicSharedMemorySize, FLASH_SMEM);

    rope_tab_kernel<<<512, 256>>>();
    cvt_all_kernel<<<8192, 256>>>(x, Wq, Wk, Wv, Wo);

    mma_gemm_kernel<0><<<dim3(3 * DM / 128, SEQ / 128), 128, GEMM_SMEM>>>(nullptr);

    flash_kernel<<<dim3(SEQ / 128, NH), 256, FLASH_SMEM>>>();

    mma_gemm_kernel<1><<<dim3(DM / 128, SEQ / 128), 128, GEMM_SMEM>>>(out);
}